// round 15
// baseline (speedup 1.0000x reference)
#include <cuda_runtime.h>
#include <cuda_fp16.h>
#include <math.h>
#include <stdint.h>

// ---------------- problem constants ----------------
#define S_SLOTS 4096
#define N_IN    16384
#define D_DIM   768
#define D3      2304
#define PV_SPLIT 8
#define PV_KSPLIT (N_IN / PV_SPLIT)   // 2048

#define BN 128
#define BKH 32                  // halves per k-stage (fp16 GEMM)
#define PADH 40                 // halves per smem row
#define PADB 80                 // bytes per smem row (fp8 GEMM)
#define STAGES 4
#define BTILE_H (128 * PADH)

#define EXP_SHIFT 2.0f
#define LOG2E 1.44269504f

// ---------------- scratch (device globals) ----------------
__device__ float g_slots [S_SLOTS * D_DIM];
__device__ float g_lsum  [S_SLOTS];
__device__ float g_gx    [S_SLOTS * D3];
__device__ float g_gh    [S_SLOTS * D3];
__device__ float g_h     [S_SLOTS * D_DIM];
__device__ float g_pvpart[(size_t)PV_SPLIT * S_SLOTS * D_DIM];
__device__ __half g_pln_h  [N_IN * D_DIM];
__device__ __half g_v_h    [N_IN * D_DIM];
__device__ __half g_slots_h[S_SLOTS * D_DIM];
__device__ __half g_tmp_h  [S_SLOTS * D_DIM];
__device__ __half g_upd_h  [S_SLOTS * D_DIM];
__device__ __half g_t_h    [S_SLOTS * D_DIM];
__device__ uint8_t g_q8  [S_SLOTS * D_DIM];          // q (e4m3)
__device__ uint8_t g_k8  [N_IN * D_DIM];             // k (e4m3)
__device__ uint8_t g_p8  [(size_t)S_SLOTS * N_IN];   // P (e4m3)
__device__ uint8_t g_vT8 [(size_t)D_DIM * N_IN];     // v^T (e4m3)
__device__ __half g_Wq [D_DIM * D_DIM];
__device__ __half g_Wk [D_DIM * D_DIM];
__device__ __half g_Wv [D_DIM * D_DIM];
__device__ __half g_W1 [D_DIM * D_DIM];
__device__ __half g_W2 [D_DIM * D_DIM];
__device__ __half g_Wih[D3 * D_DIM];
__device__ __half g_Whh[D3 * D_DIM];

// ---------------- PTX helpers ----------------
__device__ __forceinline__ uint32_t s2u(const void* p) {
    uint32_t a;
    asm("{ .reg .u64 t; cvta.to.shared.u64 t, %1; cvt.u32.u64 %0, t; }" : "=r"(a) : "l"(p));
    return a;
}

__device__ __forceinline__ void cp16(uint32_t s, const void* g) {
    asm volatile("cp.async.cg.shared.global [%0], [%1], 16;" :: "r"(s), "l"(g) : "memory");
}

__device__ __forceinline__ uint32_t ex2_h2(uint32_t x) {
    uint32_t y;
    asm("ex2.approx.f16x2 %0, %1;" : "=r"(y) : "r"(x));
    return y;
}

__device__ __forceinline__ float tanh_ap(float x) {
    float y;
    asm("tanh.approx.f32 %0, %1;" : "=f"(y) : "f"(x));
    return y;
}

__device__ __forceinline__ uint16_t pack_e4m3(float lo, float hi) {
    uint16_t r;
    asm("cvt.rn.satfinite.e4m3x2.f32 %0, %1, %2;" : "=h"(r) : "f"(hi), "f"(lo));
    return r;
}

__device__ __forceinline__ uint16_t h2_to_e4m3x2(uint32_t h2) {
    uint16_t r;
    asm("cvt.rn.satfinite.e4m3x2.f16x2 %0, %1;" : "=h"(r) : "r"(h2));
    return r;
}

__device__ __forceinline__ uint32_t e4m3x2_to_h2(uint16_t v) {
    uint32_t r;
    asm("cvt.rn.f16x2.e4m3x2 %0, %1;" : "=r"(r) : "h"(v));
    return r;
}

__device__ __forceinline__ void ldm_x4(uint32_t& r0, uint32_t& r1, uint32_t& r2,
                                       uint32_t& r3, uint32_t a) {
    asm volatile("ldmatrix.sync.aligned.m8n8.x4.shared.b16 {%0,%1,%2,%3}, [%4];"
                 : "=r"(r0), "=r"(r1), "=r"(r2), "=r"(r3) : "r"(a));
}

__device__ __forceinline__ void mma_f16(float* c, uint32_t a0, uint32_t a1,
                                        uint32_t a2, uint32_t a3,
                                        uint32_t b0, uint32_t b1) {
    asm volatile(
        "mma.sync.aligned.m16n8k16.row.col.f32.f16.f16.f32 "
        "{%0,%1,%2,%3}, {%4,%5,%6,%7}, {%8,%9}, {%0,%1,%2,%3};"
        : "+f"(c[0]), "+f"(c[1]), "+f"(c[2]), "+f"(c[3])
        : "r"(a0), "r"(a1), "r"(a2), "r"(a3), "r"(b0), "r"(b1));
}

__device__ __forceinline__ void mma_e4m3(float* c, uint32_t a0, uint32_t a1,
                                         uint32_t a2, uint32_t a3,
                                         uint32_t b0, uint32_t b1) {
    asm volatile(
        "mma.sync.aligned.m16n8k32.row.col.f32.e4m3.e4m3.f32 "
        "{%0,%1,%2,%3}, {%4,%5,%6,%7}, {%8,%9}, {%0,%1,%2,%3};"
        : "+f"(c[0]), "+f"(c[1]), "+f"(c[2]), "+f"(c[3])
        : "r"(a0), "r"(a1), "r"(a2), "r"(a3), "r"(b0), "r"(b1));
}

// ---------------- fp16 tensor-core NT GEMM (templated M-tile) ----------------
template <int MF>
__global__ void __launch_bounds__(256, MF == 4 ? 2 : 3) gemm_h(
    const __half* __restrict__ A, const __half* __restrict__ B,
    float* __restrict__ C32, __half* __restrict__ C16, uint8_t* __restrict__ C8,
    int K, int ldab, int NC, float alpha,
    const float* __restrict__ bias, const float* __restrict__ rowdiv,
    const float* __restrict__ addsrc, int relu)
{
    constexpr int TBM = MF * 32;
    constexpr int ATILE_H = TBM * PADH;
    extern __shared__ __half smh[];
    __half* As = smh;
    __half* Bs = smh + STAGES * ATILE_H;

    int tid = threadIdx.x, lane = tid & 31, wid = tid >> 5;
    int wm = wid & 1, wn = wid >> 1;
    int m0 = blockIdx.y * TBM, n0 = blockIdx.x * BN;
    int KT = K / BKH;

    int lr = tid >> 2;
    int cch = tid & 3;
    const __half* Ag = A + (size_t)(m0 + lr) * ldab + cch * 8;
    const __half* Bg = B + (size_t)(n0 + lr) * ldab + cch * 8;
    uint32_t as_u = s2u(As), bs_u = s2u(Bs);

    uint32_t a_off[MF], b_off[2];
    {
        int ar = (lane & 7) + 8 * ((lane >> 3) & 1);
        int ak = 8 * (lane >> 4);
        #pragma unroll
        for (int mf = 0; mf < MF; mf++)
            a_off[mf] = (uint32_t)((wm * (MF * 16) + mf * 16 + ar) * PADH + ak) * 2u;
        #pragma unroll
        for (int p = 0; p < 2; p++)
            b_off[p] = (uint32_t)((wn * 32 + p * 16 + ar) * PADH + ak) * 2u;
    }

    float acc[MF][4][4];
    #pragma unroll
    for (int i = 0; i < MF; i++)
        #pragma unroll
        for (int j = 0; j < 4; j++)
            #pragma unroll
            for (int q = 0; q < 4; q++) acc[i][j][q] = 0.0f;

    #pragma unroll
    for (int p = 0; p < 3; p++) {
        #pragma unroll
        for (int i = 0; i < MF / 2; i++) {
            uint32_t soff = (uint32_t)(p * ATILE_H + (lr + i * 64) * PADH) * 2u + cch * 16u;
            cp16(as_u + soff, Ag + (size_t)i * 64 * ldab + (size_t)p * BKH);
        }
        #pragma unroll
        for (int i = 0; i < 2; i++) {
            uint32_t soff = (uint32_t)(p * BTILE_H + (lr + i * 64) * PADH) * 2u + cch * 16u;
            cp16(bs_u + soff, Bg + (size_t)i * 64 * ldab + (size_t)p * BKH);
        }
        asm volatile("cp.async.commit_group;" ::: "memory");
    }

    for (int kt = 0; kt < KT; kt++) {
        asm volatile("cp.async.wait_group 2;" ::: "memory");
        __syncthreads();
        int st = kt & (STAGES - 1);
        if (kt + 3 < KT) {
            int d = (kt + 3) & (STAGES - 1);
            #pragma unroll
            for (int i = 0; i < MF / 2; i++) {
                uint32_t soff = (uint32_t)(d * ATILE_H + (lr + i * 64) * PADH) * 2u + cch * 16u;
                cp16(as_u + soff, Ag + (size_t)i * 64 * ldab + (size_t)(kt + 3) * BKH);
            }
            #pragma unroll
            for (int i = 0; i < 2; i++) {
                uint32_t soff = (uint32_t)(d * BTILE_H + (lr + i * 64) * PADH) * 2u + cch * 16u;
                cp16(bs_u + soff, Bg + (size_t)i * 64 * ldab + (size_t)(kt + 3) * BKH);
            }
        }
        asm volatile("cp.async.commit_group;" ::: "memory");

        uint32_t abase = as_u + (uint32_t)(st * ATILE_H) * 2u;
        uint32_t bbase = bs_u + (uint32_t)(st * BTILE_H) * 2u;

        #pragma unroll
        for (int ks = 0; ks < 2; ks++) {
            uint32_t koff = ks * 32u;
            uint32_t bf[4][2];
            #pragma unroll
            for (int p = 0; p < 2; p++) {
                uint32_t r0, r1, r2, r3;
                ldm_x4(r0, r1, r2, r3, bbase + b_off[p] + koff);
                bf[2 * p][0] = r0; bf[2 * p + 1][0] = r1;
                bf[2 * p][1] = r2; bf[2 * p + 1][1] = r3;
            }
            #pragma unroll
            for (int mf = 0; mf < MF; mf++) {
                uint32_t a0, a1, a2, a3;
                ldm_x4(a0, a1, a2, a3, abase + a_off[mf] + koff);
                #pragma unroll
                for (int nf = 0; nf < 4; nf++)
                    mma_f16(acc[mf][nf], a0, a1, a2, a3, bf[nf][0], bf[nf][1]);
            }
        }
    }

    // -------- epilogue --------
    int g4 = lane >> 2, q4 = lane & 3;
    int c2 = 2 * q4;
    int rbase = m0 + wm * (MF * 16) + g4;
    #pragma unroll
    for (int mf = 0; mf < MF; mf++) {
        int r1 = rbase + mf * 16;
        int r2 = r1 + 8;
        float inv1 = 1.0f, inv2 = 1.0f;
        if (rowdiv) { inv1 = 1.0f / rowdiv[r1]; inv2 = 1.0f / rowdiv[r2]; }
        #pragma unroll
        for (int nf = 0; nf < 4; nf++) {
            int col = n0 + wn * 32 + nf * 8 + c2;
            float b0 = 0.f, b1 = 0.f;
            if (bias) { b0 = bias[col]; b1 = bias[col + 1]; }
            float v00 = acc[mf][nf][0] * alpha * inv1 + b0;
            float v01 = acc[mf][nf][1] * alpha * inv1 + b1;
            float v10 = acc[mf][nf][2] * alpha * inv2 + b0;
            float v11 = acc[mf][nf][3] * alpha * inv2 + b1;
            if (relu) {
                v00 = fmaxf(v00, 0.f); v01 = fmaxf(v01, 0.f);
                v10 = fmaxf(v10, 0.f); v11 = fmaxf(v11, 0.f);
            }
            if (addsrc) {
                const float* s1 = addsrc + (size_t)r1 * NC + col;
                const float* s2 = addsrc + (size_t)r2 * NC + col;
                v00 += s1[0]; v01 += s1[1]; v10 += s2[0]; v11 += s2[1];
            }
            if (C32) {
                *(float2*)(C32 + (size_t)r1 * NC + col) = make_float2(v00, v01);
                *(float2*)(C32 + (size_t)r2 * NC + col) = make_float2(v10, v11);
            }
            if (C16) {
                *(__half2*)(C16 + (size_t)r1 * NC + col) = __floats2half2_rn(v00, v01);
                *(__half2*)(C16 + (size_t)r2 * NC + col) = __floats2half2_rn(v10, v11);
            }
            if (C8) {
                *(uint16_t*)(C8 + (size_t)r1 * NC + col) = pack_e4m3(v00, v01);
                *(uint16_t*)(C8 + (size_t)r2 * NC + col) = pack_e4m3(v10, v11);
            }
        }
    }
}

// ---------------- fp8 e4m3 NT GEMM (templated M-tile + pipeline depth) ----------
// do_exp: P = exp(acc*alpha - SHIFT) via f16x2 MUFU, stored e4m3 to C8.
// else:   fp32 partials to C32 (+ blockIdx.z slab for split-K).
template <int MF, int STG>
__global__ void __launch_bounds__(256, MF == 4 ? 2 : 3) gemm_f8(
    const uint8_t* __restrict__ A, const uint8_t* __restrict__ B,
    float* __restrict__ C32, uint8_t* __restrict__ C8,
    int K, int ldab, int NC, float alpha, int do_exp)
{
    constexpr int TBM = MF * 32;
    constexpr int ASTG = TBM * PADB;
    constexpr int BSTG = 128 * PADB;
    extern __shared__ uint8_t smb[];
    uint8_t* As = smb;
    uint8_t* Bs = smb + STG * ASTG;

    int tid = threadIdx.x, lane = tid & 31, wid = tid >> 5;
    int wm = wid & 1, wn = wid >> 1;
    int m0 = blockIdx.y * TBM, n0 = blockIdx.x * BN;
    int sk = blockIdx.z;
    int KT = K / 64;

    int lr = tid >> 2;
    int cch = tid & 3;
    const uint8_t* Ag = A + (size_t)(m0 + lr) * ldab + (size_t)sk * K + cch * 16;
    const uint8_t* Bg = B + (size_t)(n0 + lr) * ldab + (size_t)sk * K + cch * 16;
    uint32_t as_u = s2u(As), bs_u = s2u(Bs);

    if (C32) C32 += (size_t)sk * (size_t)(gridDim.y * TBM) * NC;

    int g4 = lane >> 2, q4 = lane & 3;

    float acc[MF][4][4];
    #pragma unroll
    for (int i = 0; i < MF; i++)
        #pragma unroll
        for (int j = 0; j < 4; j++)
            #pragma unroll
            for (int q = 0; q < 4; q++) acc[i][j][q] = 0.0f;

    // prologue: STG-1 stages
    #pragma unroll
    for (int p = 0; p < STG - 1; p++) {
        #pragma unroll
        for (int i = 0; i < MF / 2; i++)
            cp16(as_u + (uint32_t)(p * ASTG + (lr + i * 64) * PADB) + cch * 16u,
                 Ag + (size_t)i * 64 * ldab + (size_t)p * 64);
        #pragma unroll
        for (int i = 0; i < 2; i++)
            cp16(bs_u + (uint32_t)(p * BSTG + (lr + i * 64) * PADB) + cch * 16u,
                 Bg + (size_t)i * 64 * ldab + (size_t)p * 64);
        asm volatile("cp.async.commit_group;" ::: "memory");
    }

    int st = 0;
    for (int kt = 0; kt < KT; kt++) {
        asm volatile("cp.async.wait_group %0;" :: "n"(STG - 2) : "memory");
        __syncthreads();
        if (kt + STG - 1 < KT) {
            int d = st + (STG - 1); if (d >= STG) d -= STG;
            #pragma unroll
            for (int i = 0; i < MF / 2; i++)
                cp16(as_u + (uint32_t)(d * ASTG + (lr + i * 64) * PADB) + cch * 16u,
                     Ag + (size_t)i * 64 * ldab + (size_t)(kt + STG - 1) * 64);
            #pragma unroll
            for (int i = 0; i < 2; i++)
                cp16(bs_u + (uint32_t)(d * BSTG + (lr + i * 64) * PADB) + cch * 16u,
                     Bg + (size_t)i * 64 * ldab + (size_t)(kt + STG - 1) * 64);
        }
        asm volatile("cp.async.commit_group;" ::: "memory");

        const uint8_t* ab = As + st * ASTG;
        const uint8_t* bb = Bs + st * BSTG;

        #pragma unroll
        for (int ks = 0; ks < 2; ks++) {
            int koff = ks * 32 + q4 * 4;
            uint32_t bf[4][2];
            #pragma unroll
            for (int nf = 0; nf < 4; nf++) {
                const uint8_t* bp = bb + (wn * 32 + nf * 8 + g4) * PADB + koff;
                bf[nf][0] = *(const uint32_t*)bp;
                bf[nf][1] = *(const uint32_t*)(bp + 16);
            }
            #pragma unroll
            for (int mf = 0; mf < MF; mf++) {
                const uint8_t* ap = ab + (wm * (MF * 16) + mf * 16 + g4) * PADB + koff;
                uint32_t a0 = *(const uint32_t*)ap;
                uint32_t a1 = *(const uint32_t*)(ap + 8 * PADB);
                uint32_t a2 = *(const uint32_t*)(ap + 16);
                uint32_t a3 = *(const uint32_t*)(ap + 8 * PADB + 16);
                #pragma unroll
                for (int nf = 0; nf < 4; nf++)
                    mma_e4m3(acc[mf][nf], a0, a1, a2, a3, bf[nf][0], bf[nf][1]);
            }
        }
        st++; if (st == STG) st = 0;
    }

    int c2 = 2 * q4;
    int rbase = m0 + wm * (MF * 16) + g4;
    #pragma unroll
    for (int mf = 0; mf < MF; mf++) {
        int r1 = rbase + mf * 16, r2 = r1 + 8;
        #pragma unroll
        for (int nf = 0; nf < 4; nf++) {
            int col = n0 + wn * 32 + nf * 8 + c2;
            if (do_exp) {
                float a00 = (acc[mf][nf][0] * alpha - EXP_SHIFT) * LOG2E;
                float a01 = (acc[mf][nf][1] * alpha - EXP_SHIFT) * LOG2E;
                float a10 = (acc[mf][nf][2] * alpha - EXP_SHIFT) * LOG2E;
                float a11 = (acc[mf][nf][3] * alpha - EXP_SHIFT) * LOG2E;
                __half2 h0 = __floats2half2_rn(a00, a01);
                __half2 h1 = __floats2half2_rn(a10, a11);
                uint32_t e0 = ex2_h2(*(uint32_t*)&h0);
                uint32_t e1 = ex2_h2(*(uint32_t*)&h1);
                *(uint16_t*)(C8 + (size_t)r1 * NC + col) = h2_to_e4m3x2(e0);
                *(uint16_t*)(C8 + (size_t)r2 * NC + col) = h2_to_e4m3x2(e1);
            } else {
                *(float2*)(C32 + (size_t)r1 * NC + col) =
                    make_float2(acc[mf][nf][0], acc[mf][nf][1]);
                *(float2*)(C32 + (size_t)r2 * NC + col) =
                    make_float2(acc[mf][nf][2], acc[mf][nf][3]);
            }
        }
    }
}

#define GEMM_SMEM_4 (STAGES * (128 * PADH + 128 * PADH) * 2)   // 81920
#define GEMM_SMEM_2 (STAGES * (64 * PADH + 128 * PADH) * 2)    // 61440
#define F8_SMEM_PV  (4 * (64 * PADB + 128 * PADB))             // 61440
#define F8_SMEM_QK  (3 * (64 * PADB + 128 * PADB))             // 46080

// ---------------- reductions ----------------
__device__ __forceinline__ float blk_sum(float v, float* sm) {
    #pragma unroll
    for (int o = 16; o; o >>= 1) v += __shfl_xor_sync(0xffffffffu, v, o);
    int w = threadIdx.x >> 5;
    if ((threadIdx.x & 31) == 0) sm[w] = v;
    __syncthreads();
    if (threadIdx.x < 8) {
        float x = sm[threadIdx.x];
        #pragma unroll
        for (int o = 4; o; o >>= 1) x += __shfl_xor_sync(0xffu, x, o);
        if (threadIdx.x == 0) sm[0] = x;
    }
    __syncthreads();
    float r = sm[0];
    __syncthreads();
    return r;
}

// ---------------- elementwise kernels ----------------
__global__ void to_half_kernel(const float* __restrict__ in, __half* __restrict__ out, int n) {
    int i = blockIdx.x * 256 + threadIdx.x;
    if (i < n) out[i] = __float2half_rn(in[i]);
}

__global__ void copy_both_kernel(const float* __restrict__ in, float* __restrict__ o32,
                                 __half* __restrict__ o16, int n) {
    int i = blockIdx.x * 256 + threadIdx.x;
    if (i < n) { float v = in[i]; o32[i] = v; o16[i] = __float2half_rn(v); }
}

__global__ void reduce_pv_kernel(const float* __restrict__ part, __half* __restrict__ out) {
    int i = blockIdx.x * 256 + threadIdx.x;
    float s = 0.0f;
    #pragma unroll
    for (int k = 0; k < PV_SPLIT; k++)
        s += part[(size_t)k * S_SLOTS * D_DIM + i];
    out[i] = __float2half_rn(s);
}

__global__ void __launch_bounds__(256) ln_h_kernel(
    const float* __restrict__ x, const float* __restrict__ g,
    const float* __restrict__ be, __half* __restrict__ y)
{
    __shared__ float sm[8];
    int row = blockIdx.x;
    const float* xr = x + (size_t)row * D_DIM;
    int t = threadIdx.x;
    float v0 = xr[t], v1 = xr[t + 256], v2 = xr[t + 512];
    float s = blk_sum(v0 + v1 + v2, sm);
    float mean = s * (1.0f / 768.0f);
    float d0 = v0 - mean, d1 = v1 - mean, d2 = v2 - mean;
    float ss = blk_sum(d0 * d0 + d1 * d1 + d2 * d2, sm);
    float inv = rsqrtf(ss * (1.0f / 768.0f) + 1e-5f);
    __half* yr = y + (size_t)row * D_DIM;
    yr[t]       = __float2half_rn(d0 * inv * g[t]       + be[t]);
    yr[t + 256] = __float2half_rn(d1 * inv * g[t + 256] + be[t + 256]);
    yr[t + 512] = __float2half_rn(d2 * inv * g[t + 512] + be[t + 512]);
}

// row sums of e4m3 P -> lsum (fp32)
__global__ void __launch_bounds__(256) rowsum8_kernel(
    const uint8_t* __restrict__ p, float* __restrict__ lsum)
{
    __shared__ float sm[8];
    int row = blockIdx.x;
    const uint32_t* pr = (const uint32_t*)(p + (size_t)row * N_IN);
    float s = 0.0f;
    #pragma unroll
    for (int i = 0; i < 16; i++) {
        uint32_t w = pr[threadIdx.x + i * 256];
        uint32_t f0 = e4m3x2_to_h2((uint16_t)(w & 0xFFFFu));
        uint32_t f1 = e4m3x2_to_h2((uint16_t)(w >> 16));
        float2 a = __half22float2(*(__half2*)&f0);
        float2 b = __half22float2(*(__half2*)&f1);
        s += (a.x + a.y) + (b.x + b.y);
    }
    s = blk_sum(s, sm);
    if (threadIdx.x == 0) lsum[row] = s;
}

// v_h [N_IN, D_DIM] fp16 -> vT8 [D_DIM, N_IN] e4m3
__global__ void transpose_8(const __half* __restrict__ in, uint8_t* __restrict__ out) {
    __shared__ __half t[32][33];
    int c0 = blockIdx.x * 32, r0 = blockIdx.y * 32;
    for (int i = threadIdx.y; i < 32; i += 8)
        t[i][threadIdx.x] = in[(size_t)(r0 + i) * D_DIM + c0 + threadIdx.x];
    __syncthreads();
    for (int i = threadIdx.y; i < 32; i += 8) {
        float f = __half2float(t[threadIdx.x][i]);
        out[(size_t)(c0 + i) * N_IN + r0 + threadIdx.x] = (uint8_t)pack_e4m3(f, 0.0f);
    }
}

// fused GRU + LayerNorm(h): one block per row
__global__ void __launch_bounds__(256) gru_ln_kernel(
    const float* __restrict__ gx, const float* __restrict__ gh,
    const float* __restrict__ sp, float* __restrict__ hout,
    const float* __restrict__ g, const float* __restrict__ be,
    __half* __restrict__ y)
{
    __shared__ float sm[8];
    int row = blockIdx.x;
    int t = threadIdx.x;
    size_t b3 = (size_t)row * D3;
    size_t b1 = (size_t)row * D_DIM;
    float hv[3];
    #pragma unroll
    for (int j = 0; j < 3; j++) {
        int d = t + j * 256;
        float xr = gx[b3 + d], xz = gx[b3 + D_DIM + d], xn = gx[b3 + 2 * D_DIM + d];
        float hr = gh[b3 + d], hz = gh[b3 + D_DIM + d], hn = gh[b3 + 2 * D_DIM + d];
        float r = 0.5f + 0.5f * tanh_ap(0.5f * (xr + hr));
        float z = 0.5f + 0.5f * tanh_ap(0.5f * (xz + hz));
        float n = tanh_ap(xn + r * hn);
        hv[j] = (1.0f - z) * n + z * sp[b1 + d];
        hout[b1 + d] = hv[j];
    }
    float s = blk_sum(hv[0] + hv[1] + hv[2], sm);
    float mean = s * (1.0f / 768.0f);
    float d0 = hv[0] - mean, d1 = hv[1] - mean, d2 = hv[2] - mean;
    float ss = blk_sum(d0 * d0 + d1 * d1 + d2 * d2, sm);
    float inv = rsqrtf(ss * (1.0f / 768.0f) + 1e-5f);
    __half* yr = y + b1;
    yr[t]       = __float2half_rn(d0 * inv * g[t]       + be[t]);
    yr[t + 256] = __float2half_rn(d1 * inv * g[t + 256] + be[t + 256]);
    yr[t + 512] = __float2half_rn(d2 * inv * g[t + 512] + be[t + 512]);
}

// ---------------- host launch ----------------
static void launch_gemm4(const __half* A, const __half* B, float* C32, __half* C16,
                         uint8_t* C8, int M, int N, int K, float alpha,
                         const float* bias, const float* rowdiv, const float* addsrc,
                         int relu, cudaStream_t st = 0)
{
    dim3 g(N / BN, M / 128, 1);
    gemm_h<4><<<g, 256, GEMM_SMEM_4, st>>>(A, B, C32, C16, C8, K, K, N, alpha, bias,
                                           rowdiv, addsrc, relu);
}

static void launch_gemm2(const __half* A, const __half* B, float* C32, __half* C16,
                         uint8_t* C8, int M, int N, int K, float alpha,
                         const float* bias, const float* rowdiv, const float* addsrc,
                         int relu, cudaStream_t st = 0)
{
    dim3 g(N / BN, M / 64, 1);
    gemm_h<2><<<g, 256, GEMM_SMEM_2, st>>>(A, B, C32, C16, C8, K, K, N, alpha, bias,
                                           rowdiv, addsrc, relu);
}

extern "C" void kernel_launch(void* const* d_in, const int* in_sizes, int n_in,
                              void* d_out, int out_size)
{
    (void)in_sizes; (void)n_in; (void)out_size;
    const float* cand = (const float*)d_in[0];
    const float* pano = (const float*)d_in[1];
    const float* Wq   = (const float*)d_in[2];
    const float* bq   = (const float*)d_in[3];
    const float* Wk   = (const float*)d_in[4];
    const float* bk   = (const float*)d_in[5];
    const float* Wv   = (const float*)d_in[6];
    const float* bv   = (const float*)d_in[7];
    const float* Wih  = (const float*)d_in[8];
    const float* bih  = (const float*)d_in[9];
    const float* Whh  = (const float*)d_in[10];
    const float* bhh  = (const float*)d_in[11];
    const float* W1   = (const float*)d_in[12];
    const float* b1   = (const float*)d_in[13];
    const float* W2   = (const float*)d_in[14];
    const float* b2   = (const float*)d_in[15];
    const float* gin  = (const float*)d_in[16];
    const float* bein = (const float*)d_in[17];
    const float* gsl  = (const float*)d_in[18];
    const float* besl = (const float*)d_in[19];
    const float* gff  = (const float*)d_in[20];
    const float* beff = (const float*)d_in[21];

    cudaFuncSetAttribute(gemm_h<4>, cudaFuncAttributeMaxDynamicSharedMemorySize, GEMM_SMEM_4);
    cudaFuncSetAttribute(gemm_h<2>, cudaFuncAttributeMaxDynamicSharedMemorySize, GEMM_SMEM_2);
    cudaFuncSetAttribute((void(*)(const uint8_t*, const uint8_t*, float*, uint8_t*,
                                  int, int, int, float, int))gemm_f8<2, 4>,
                         cudaFuncAttributeMaxDynamicSharedMemorySize, F8_SMEM_PV);
    cudaFuncSetAttribute((void(*)(const uint8_t*, const uint8_t*, float*, uint8_t*,
                                  int, int, int, float, int))gemm_f8<2, 3>,
                         cudaFuncAttributeMaxDynamicSharedMemorySize, F8_SMEM_QK);

    float *pslots, *pl, *pgx, *pgh, *ph, *ppart;
    __half *pln_h, *pv_h, *pslots_h, *ptmp_h, *pupd_h, *pt_h;
    uint8_t *pq8, *pk8, *pp8, *pvT8;
    __half *wq, *wk, *wv, *w1, *w2, *wih, *whh;
    cudaGetSymbolAddress((void**)&pslots,  g_slots);
    cudaGetSymbolAddress((void**)&pl,      g_lsum);
    cudaGetSymbolAddress((void**)&pgx,     g_gx);
    cudaGetSymbolAddress((void**)&pgh,     g_gh);
    cudaGetSymbolAddress((void**)&ph,      g_h);
    cudaGetSymbolAddress((void**)&ppart,   g_pvpart);
    cudaGetSymbolAddress((void**)&pln_h,   g_pln_h);
    cudaGetSymbolAddress((void**)&pv_h,    g_v_h);
    cudaGetSymbolAddress((void**)&pslots_h,g_slots_h);
    cudaGetSymbolAddress((void**)&ptmp_h,  g_tmp_h);
    cudaGetSymbolAddress((void**)&pupd_h,  g_upd_h);
    cudaGetSymbolAddress((void**)&pt_h,    g_t_h);
    cudaGetSymbolAddress((void**)&pq8,     g_q8);
    cudaGetSymbolAddress((void**)&pk8,     g_k8);
    cudaGetSymbolAddress((void**)&pp8,     g_p8);
    cudaGetSymbolAddress((void**)&pvT8,    g_vT8);
    cudaGetSymbolAddress((void**)&wq,      g_Wq);
    cudaGetSymbolAddress((void**)&wk,      g_Wk);
    cudaGetSymbolAddress((void**)&wv,      g_Wv);
    cudaGetSymbolAddress((void**)&w1,      g_W1);
    cudaGetSymbolAddress((void**)&w2,      g_W2);
    cudaGetSymbolAddress((void**)&wih,     g_Wih);
    cudaGetSymbolAddress((void**)&whh,     g_Whh);

    const float scale = 1.0f / sqrtf((float)D_DIM);
    const int DD = D_DIM * D_DIM, D3D = D3 * D_DIM;

    cudaStream_t s2;
    cudaStreamCreateWithFlags(&s2, cudaStreamNonBlocking);
    cudaEvent_t evF[4], evJa[4], evJb[4];
    for (int i = 0; i < 4; i++) {
        cudaEventCreateWithFlags(&evF[i],  cudaEventDisableTiming);
        cudaEventCreateWithFlags(&evJa[i], cudaEventDisableTiming);
        cudaEventCreateWithFlags(&evJb[i], cudaEventDisableTiming);
    }

    // ---- setup ----
    to_half_kernel<<<(DD + 255) / 256, 256>>>(Wk, wk, DD);
    to_half_kernel<<<(DD + 255) / 256, 256>>>(Wv, wv, DD);
    ln_h_kernel<<<N_IN, 256>>>(pano, gin, bein, pln_h);

    cudaEventRecord(evF[3], 0);
    cudaStreamWaitEvent(s2, evF[3], 0);
    to_half_kernel<<<(DD + 255) / 256, 256, 0, s2>>>(Wq, wq, DD);
    to_half_kernel<<<(DD + 255) / 256, 256, 0, s2>>>(W1, w1, DD);
    to_half_kernel<<<(DD + 255) / 256, 256, 0, s2>>>(W2, w2, DD);
    to_half_kernel<<<(D3D + 255) / 256, 256, 0, s2>>>(Wih, wih, D3D);
    to_half_kernel<<<(D3D + 255) / 256, 256, 0, s2>>>(Whh, whh, D3D);
    cudaEventRecord(evJa[3], s2);

    // kproj -> e4m3, vproj -> fp16 -> transpose to e4m3
    launch_gemm4(pln_h, wk, 0, 0, pk8, N_IN, D_DIM, D_DIM, 1.0f, bk, 0, 0, 0);
    launch_gemm4(pln_h, wv, 0, pv_h, 0, N_IN, D_DIM, D_DIM, 1.0f, bv, 0, 0, 0);
    transpose_8<<<dim3(D_DIM / 32, N_IN / 32), dim3(32, 8)>>>(pv_h, pvT8);
    copy_both_kernel<<<(S_SLOTS * D_DIM) / 256, 256>>>(cand, pslots, pslots_h, S_SLOTS * D_DIM);
    cudaStreamWaitEvent(0, evJa[3], 0);

    for (int it = 0; it < 3; ++it) {
        // critical path: LN, qproj (-> e4m3), fp8 QK (high-occupancy 64x128, 3-stage)
        ln_h_kernel<<<S_SLOTS, 256>>>(pslots, gsl, besl, ptmp_h);
        launch_gemm2(ptmp_h, wq, 0, 0, pq8, S_SLOTS, D_DIM, D_DIM, 1.0f, bq, 0, 0, 0);
        {
            dim3 g(N_IN / BN, S_SLOTS / 64, 1);
            gemm_f8<2, 3><<<g, 256, F8_SMEM_QK>>>(pq8, pk8, 0, pp8, D_DIM, D_DIM, N_IN,
                                                  scale, 1);
        }

        // fork after QK: rowsum then gh on s2
        cudaEventRecord(evF[it], 0);
        cudaStreamWaitEvent(s2, evF[it], 0);
        rowsum8_kernel<<<S_SLOTS, 256, 0, s2>>>(pp8, pl);
        cudaEventRecord(evJa[it], s2);
        launch_gemm4(pslots_h, whh, pgh, 0, 0, S_SLOTS, D3, D_DIM, 1.0f, bhh, 0, 0, 0, s2);
        cudaEventRecord(evJb[it], s2);

        // P@V split-K in fp8, reduce -> upd_h
        {
            dim3 g(D_DIM / BN, S_SLOTS / 64, PV_SPLIT);
            gemm_f8<2, 4><<<g, 256, F8_SMEM_PV>>>(pp8, pvT8, ppart, 0, PV_KSPLIT, N_IN,
                                                  D_DIM, 1.0f, 0);
        }
        reduce_pv_kernel<<<(S_SLOTS * D_DIM) / 256, 256>>>(ppart, pupd_h);

        // gx = (upd_raw @ Wih^T)/lsum + bih
        cudaStreamWaitEvent(0, evJa[it], 0);
        launch_gemm4(pupd_h, wih, pgx, 0, 0, S_SLOTS, D3, D_DIM, 1.0f, bih, pl, 0, 0);

        // fused GRU + ff-LN (needs gh)
        cudaStreamWaitEvent(0, evJb[it], 0);
        gru_ln_kernel<<<S_SLOTS, 256>>>(pgx, pgh, pslots, ph, gff, beff, ptmp_h);

        // slots = h + relu(LN(h) @ W1^T + b1) @ W2^T + b2
        launch_gemm2(ptmp_h, w1, 0, pt_h, 0, S_SLOTS, D_DIM, D_DIM, 1.0f, b1, 0, 0, 1);
        if (it == 2) {
            launch_gemm2(pt_h, w2, (float*)d_out, 0, 0, S_SLOTS, D_DIM, D_DIM, 1.0f, b2, 0, ph, 0);
        } else {
            launch_gemm2(pt_h, w2, pslots, pslots_h, 0, S_SLOTS, D_DIM, D_DIM, 1.0f, b2, 0, ph, 0);
        }
    }
}

// round 16
// speedup vs baseline: 1.0239x; 1.0239x over previous
#include <cuda_runtime.h>
#include <cuda_fp16.h>
#include <math.h>
#include <stdint.h>

// ---------------- problem constants ----------------
#define S_SLOTS 4096
#define N_IN    16384
#define D_DIM   768
#define D3      2304
#define PV_SPLIT 8
#define PV_KSPLIT (N_IN / PV_SPLIT)   // 2048

#define BN 128
#define BKH 32                  // halves per k-stage (fp16 GEMM)
#define PADH 40                 // halves per smem row
#define PADB 80                 // bytes per smem row (fp8 GEMM)
#define STAGES 4
#define BTILE_H (128 * PADH)

#define EXP_SHIFT 2.0f
#define LOG2E 1.44269504f

// ---------------- scratch (device globals) ----------------
__device__ float g_slots [S_SLOTS * D_DIM];
__device__ float g_lsum  [S_SLOTS];
__device__ float g_gx    [S_SLOTS * D3];
__device__ float g_gh    [S_SLOTS * D3];
__device__ float g_h     [S_SLOTS * D_DIM];
__device__ float g_pvpart[(size_t)PV_SPLIT * S_SLOTS * D_DIM];
__device__ __half g_slots_h[S_SLOTS * D_DIM];
__device__ __half g_tmp_h  [S_SLOTS * D_DIM];
__device__ __half g_upd_h  [S_SLOTS * D_DIM];
__device__ __half g_t_h    [S_SLOTS * D_DIM];
__device__ uint8_t g_pln8[N_IN * D_DIM];             // LN(pano) (e4m3)
__device__ uint8_t g_q8  [S_SLOTS * D_DIM];          // q (e4m3)
__device__ uint8_t g_k8  [N_IN * D_DIM];             // k (e4m3)
__device__ uint8_t g_v8  [N_IN * D_DIM];             // v (e4m3)
__device__ uint8_t g_p8  [(size_t)S_SLOTS * N_IN];   // P (e4m3)
__device__ uint8_t g_vT8 [(size_t)D_DIM * N_IN];     // v^T (e4m3)
__device__ uint8_t g_Wk8 [D_DIM * D_DIM];
__device__ uint8_t g_Wv8 [D_DIM * D_DIM];
__device__ __half g_Wq [D_DIM * D_DIM];
__device__ __half g_W1 [D_DIM * D_DIM];
__device__ __half g_W2 [D_DIM * D_DIM];
__device__ __half g_Wih[D3 * D_DIM];
__device__ __half g_Whh[D3 * D_DIM];

// ---------------- PTX helpers ----------------
__device__ __forceinline__ uint32_t s2u(const void* p) {
    uint32_t a;
    asm("{ .reg .u64 t; cvta.to.shared.u64 t, %1; cvt.u32.u64 %0, t; }" : "=r"(a) : "l"(p));
    return a;
}

__device__ __forceinline__ void cp16(uint32_t s, const void* g) {
    asm volatile("cp.async.cg.shared.global [%0], [%1], 16;" :: "r"(s), "l"(g) : "memory");
}

__device__ __forceinline__ uint32_t ex2_h2(uint32_t x) {
    uint32_t y;
    asm("ex2.approx.f16x2 %0, %1;" : "=r"(y) : "r"(x));
    return y;
}

__device__ __forceinline__ float tanh_ap(float x) {
    float y;
    asm("tanh.approx.f32 %0, %1;" : "=f"(y) : "f"(x));
    return y;
}

__device__ __forceinline__ uint16_t pack_e4m3(float lo, float hi) {
    uint16_t r;
    asm("cvt.rn.satfinite.e4m3x2.f32 %0, %1, %2;" : "=h"(r) : "f"(hi), "f"(lo));
    return r;
}

__device__ __forceinline__ uint16_t h2_to_e4m3x2(uint32_t h2) {
    uint16_t r;
    asm("cvt.rn.satfinite.e4m3x2.f16x2 %0, %1;" : "=h"(r) : "r"(h2));
    return r;
}

__device__ __forceinline__ uint32_t e4m3x2_to_h2(uint16_t v) {
    uint32_t r;
    asm("cvt.rn.f16x2.e4m3x2 %0, %1;" : "=r"(r) : "h"(v));
    return r;
}

__device__ __forceinline__ void ldm_x4(uint32_t& r0, uint32_t& r1, uint32_t& r2,
                                       uint32_t& r3, uint32_t a) {
    asm volatile("ldmatrix.sync.aligned.m8n8.x4.shared.b16 {%0,%1,%2,%3}, [%4];"
                 : "=r"(r0), "=r"(r1), "=r"(r2), "=r"(r3) : "r"(a));
}

__device__ __forceinline__ void mma_f16(float* c, uint32_t a0, uint32_t a1,
                                        uint32_t a2, uint32_t a3,
                                        uint32_t b0, uint32_t b1) {
    asm volatile(
        "mma.sync.aligned.m16n8k16.row.col.f32.f16.f16.f32 "
        "{%0,%1,%2,%3}, {%4,%5,%6,%7}, {%8,%9}, {%0,%1,%2,%3};"
        : "+f"(c[0]), "+f"(c[1]), "+f"(c[2]), "+f"(c[3])
        : "r"(a0), "r"(a1), "r"(a2), "r"(a3), "r"(b0), "r"(b1));
}

__device__ __forceinline__ void mma_e4m3(float* c, uint32_t a0, uint32_t a1,
                                         uint32_t a2, uint32_t a3,
                                         uint32_t b0, uint32_t b1) {
    asm volatile(
        "mma.sync.aligned.m16n8k32.row.col.f32.e4m3.e4m3.f32 "
        "{%0,%1,%2,%3}, {%4,%5,%6,%7}, {%8,%9}, {%0,%1,%2,%3};"
        : "+f"(c[0]), "+f"(c[1]), "+f"(c[2]), "+f"(c[3])
        : "r"(a0), "r"(a1), "r"(a2), "r"(a3), "r"(b0), "r"(b1));
}

// ---------------- fp16 tensor-core NT GEMM (templated M-tile) ----------------
template <int MF>
__global__ void __launch_bounds__(256, MF == 4 ? 2 : 3) gemm_h(
    const __half* __restrict__ A, const __half* __restrict__ B,
    float* __restrict__ C32, __half* __restrict__ C16, uint8_t* __restrict__ C8,
    int K, int ldab, int NC, float alpha,
    const float* __restrict__ bias, const float* __restrict__ rowdiv,
    const float* __restrict__ addsrc, int relu)
{
    constexpr int TBM = MF * 32;
    constexpr int ATILE_H = TBM * PADH;
    extern __shared__ __half smh[];
    __half* As = smh;
    __half* Bs = smh + STAGES * ATILE_H;

    int tid = threadIdx.x, lane = tid & 31, wid = tid >> 5;
    int wm = wid & 1, wn = wid >> 1;
    int m0 = blockIdx.y * TBM, n0 = blockIdx.x * BN;
    int KT = K / BKH;

    int lr = tid >> 2;
    int cch = tid & 3;
    const __half* Ag = A + (size_t)(m0 + lr) * ldab + cch * 8;
    const __half* Bg = B + (size_t)(n0 + lr) * ldab + cch * 8;
    uint32_t as_u = s2u(As), bs_u = s2u(Bs);

    uint32_t a_off[MF], b_off[2];
    {
        int ar = (lane & 7) + 8 * ((lane >> 3) & 1);
        int ak = 8 * (lane >> 4);
        #pragma unroll
        for (int mf = 0; mf < MF; mf++)
            a_off[mf] = (uint32_t)((wm * (MF * 16) + mf * 16 + ar) * PADH + ak) * 2u;
        #pragma unroll
        for (int p = 0; p < 2; p++)
            b_off[p] = (uint32_t)((wn * 32 + p * 16 + ar) * PADH + ak) * 2u;
    }

    float acc[MF][4][4];
    #pragma unroll
    for (int i = 0; i < MF; i++)
        #pragma unroll
        for (int j = 0; j < 4; j++)
            #pragma unroll
            for (int q = 0; q < 4; q++) acc[i][j][q] = 0.0f;

    #pragma unroll
    for (int p = 0; p < 3; p++) {
        #pragma unroll
        for (int i = 0; i < MF / 2; i++) {
            uint32_t soff = (uint32_t)(p * ATILE_H + (lr + i * 64) * PADH) * 2u + cch * 16u;
            cp16(as_u + soff, Ag + (size_t)i * 64 * ldab + (size_t)p * BKH);
        }
        #pragma unroll
        for (int i = 0; i < 2; i++) {
            uint32_t soff = (uint32_t)(p * BTILE_H + (lr + i * 64) * PADH) * 2u + cch * 16u;
            cp16(bs_u + soff, Bg + (size_t)i * 64 * ldab + (size_t)p * BKH);
        }
        asm volatile("cp.async.commit_group;" ::: "memory");
    }

    for (int kt = 0; kt < KT; kt++) {
        asm volatile("cp.async.wait_group 2;" ::: "memory");
        __syncthreads();
        int st = kt & (STAGES - 1);
        if (kt + 3 < KT) {
            int d = (kt + 3) & (STAGES - 1);
            #pragma unroll
            for (int i = 0; i < MF / 2; i++) {
                uint32_t soff = (uint32_t)(d * ATILE_H + (lr + i * 64) * PADH) * 2u + cch * 16u;
                cp16(as_u + soff, Ag + (size_t)i * 64 * ldab + (size_t)(kt + 3) * BKH);
            }
            #pragma unroll
            for (int i = 0; i < 2; i++) {
                uint32_t soff = (uint32_t)(d * BTILE_H + (lr + i * 64) * PADH) * 2u + cch * 16u;
                cp16(bs_u + soff, Bg + (size_t)i * 64 * ldab + (size_t)(kt + 3) * BKH);
            }
        }
        asm volatile("cp.async.commit_group;" ::: "memory");

        uint32_t abase = as_u + (uint32_t)(st * ATILE_H) * 2u;
        uint32_t bbase = bs_u + (uint32_t)(st * BTILE_H) * 2u;

        #pragma unroll
        for (int ks = 0; ks < 2; ks++) {
            uint32_t koff = ks * 32u;
            uint32_t bf[4][2];
            #pragma unroll
            for (int p = 0; p < 2; p++) {
                uint32_t r0, r1, r2, r3;
                ldm_x4(r0, r1, r2, r3, bbase + b_off[p] + koff);
                bf[2 * p][0] = r0; bf[2 * p + 1][0] = r1;
                bf[2 * p][1] = r2; bf[2 * p + 1][1] = r3;
            }
            #pragma unroll
            for (int mf = 0; mf < MF; mf++) {
                uint32_t a0, a1, a2, a3;
                ldm_x4(a0, a1, a2, a3, abase + a_off[mf] + koff);
                #pragma unroll
                for (int nf = 0; nf < 4; nf++)
                    mma_f16(acc[mf][nf], a0, a1, a2, a3, bf[nf][0], bf[nf][1]);
            }
        }
    }

    // -------- epilogue --------
    int g4 = lane >> 2, q4 = lane & 3;
    int c2 = 2 * q4;
    int rbase = m0 + wm * (MF * 16) + g4;
    #pragma unroll
    for (int mf = 0; mf < MF; mf++) {
        int r1 = rbase + mf * 16;
        int r2 = r1 + 8;
        float inv1 = 1.0f, inv2 = 1.0f;
        if (rowdiv) { inv1 = 1.0f / rowdiv[r1]; inv2 = 1.0f / rowdiv[r2]; }
        #pragma unroll
        for (int nf = 0; nf < 4; nf++) {
            int col = n0 + wn * 32 + nf * 8 + c2;
            float b0 = 0.f, b1 = 0.f;
            if (bias) { b0 = bias[col]; b1 = bias[col + 1]; }
            float v00 = acc[mf][nf][0] * alpha * inv1 + b0;
            float v01 = acc[mf][nf][1] * alpha * inv1 + b1;
            float v10 = acc[mf][nf][2] * alpha * inv2 + b0;
            float v11 = acc[mf][nf][3] * alpha * inv2 + b1;
            if (relu) {
                v00 = fmaxf(v00, 0.f); v01 = fmaxf(v01, 0.f);
                v10 = fmaxf(v10, 0.f); v11 = fmaxf(v11, 0.f);
            }
            if (addsrc) {
                const float* s1 = addsrc + (size_t)r1 * NC + col;
                const float* s2 = addsrc + (size_t)r2 * NC + col;
                v00 += s1[0]; v01 += s1[1]; v10 += s2[0]; v11 += s2[1];
            }
            if (C32) {
                *(float2*)(C32 + (size_t)r1 * NC + col) = make_float2(v00, v01);
                *(float2*)(C32 + (size_t)r2 * NC + col) = make_float2(v10, v11);
            }
            if (C16) {
                *(__half2*)(C16 + (size_t)r1 * NC + col) = __floats2half2_rn(v00, v01);
                *(__half2*)(C16 + (size_t)r2 * NC + col) = __floats2half2_rn(v10, v11);
            }
            if (C8) {
                *(uint16_t*)(C8 + (size_t)r1 * NC + col) = pack_e4m3(v00, v01);
                *(uint16_t*)(C8 + (size_t)r2 * NC + col) = pack_e4m3(v10, v11);
            }
        }
    }
}

// ---------------- fp8 e4m3 NT GEMM (templated M-tile + pipeline depth) ----------
// do_exp: P = exp(acc*alpha - SHIFT) via f16x2 MUFU, stored e4m3 to C8.
// else:   v = acc*alpha (+bias); store e4m3 to C8 if given, else fp32 to C32
//         (+ blockIdx.z slab for split-K partials).
template <int MF, int STG>
__global__ void __launch_bounds__(256, MF == 4 ? 2 : 3) gemm_f8(
    const uint8_t* __restrict__ A, const uint8_t* __restrict__ B,
    float* __restrict__ C32, uint8_t* __restrict__ C8,
    int K, int ldab, int NC, float alpha,
    const float* __restrict__ bias, int do_exp)
{
    constexpr int TBM = MF * 32;
    constexpr int ASTG = TBM * PADB;
    constexpr int BSTG = 128 * PADB;
    extern __shared__ uint8_t smb[];
    uint8_t* As = smb;
    uint8_t* Bs = smb + STG * ASTG;

    int tid = threadIdx.x, lane = tid & 31, wid = tid >> 5;
    int wm = wid & 1, wn = wid >> 1;
    int m0 = blockIdx.y * TBM, n0 = blockIdx.x * BN;
    int sk = blockIdx.z;
    int KT = K / 64;

    int lr = tid >> 2;
    int cch = tid & 3;
    const uint8_t* Ag = A + (size_t)(m0 + lr) * ldab + (size_t)sk * K + cch * 16;
    const uint8_t* Bg = B + (size_t)(n0 + lr) * ldab + (size_t)sk * K + cch * 16;
    uint32_t as_u = s2u(As), bs_u = s2u(Bs);

    if (C32) C32 += (size_t)sk * (size_t)(gridDim.y * TBM) * NC;

    int g4 = lane >> 2, q4 = lane & 3;

    float acc[MF][4][4];
    #pragma unroll
    for (int i = 0; i < MF; i++)
        #pragma unroll
        for (int j = 0; j < 4; j++)
            #pragma unroll
            for (int q = 0; q < 4; q++) acc[i][j][q] = 0.0f;

    #pragma unroll
    for (int p = 0; p < STG - 1; p++) {
        #pragma unroll
        for (int i = 0; i < MF / 2; i++)
            cp16(as_u + (uint32_t)(p * ASTG + (lr + i * 64) * PADB) + cch * 16u,
                 Ag + (size_t)i * 64 * ldab + (size_t)p * 64);
        #pragma unroll
        for (int i = 0; i < 2; i++)
            cp16(bs_u + (uint32_t)(p * BSTG + (lr + i * 64) * PADB) + cch * 16u,
                 Bg + (size_t)i * 64 * ldab + (size_t)p * 64);
        asm volatile("cp.async.commit_group;" ::: "memory");
    }

    int st = 0;
    for (int kt = 0; kt < KT; kt++) {
        asm volatile("cp.async.wait_group %0;" :: "n"(STG - 2) : "memory");
        __syncthreads();
        if (kt + STG - 1 < KT) {
            int d = st + (STG - 1); if (d >= STG) d -= STG;
            #pragma unroll
            for (int i = 0; i < MF / 2; i++)
                cp16(as_u + (uint32_t)(d * ASTG + (lr + i * 64) * PADB) + cch * 16u,
                     Ag + (size_t)i * 64 * ldab + (size_t)(kt + STG - 1) * 64);
            #pragma unroll
            for (int i = 0; i < 2; i++)
                cp16(bs_u + (uint32_t)(d * BSTG + (lr + i * 64) * PADB) + cch * 16u,
                     Bg + (size_t)i * 64 * ldab + (size_t)(kt + STG - 1) * 64);
        }
        asm volatile("cp.async.commit_group;" ::: "memory");

        const uint8_t* ab = As + st * ASTG;
        const uint8_t* bb = Bs + st * BSTG;

        #pragma unroll
        for (int ks = 0; ks < 2; ks++) {
            int koff = ks * 32 + q4 * 4;
            uint32_t bf[4][2];
            #pragma unroll
            for (int nf = 0; nf < 4; nf++) {
                const uint8_t* bp = bb + (wn * 32 + nf * 8 + g4) * PADB + koff;
                bf[nf][0] = *(const uint32_t*)bp;
                bf[nf][1] = *(const uint32_t*)(bp + 16);
            }
            #pragma unroll
            for (int mf = 0; mf < MF; mf++) {
                const uint8_t* ap = ab + (wm * (MF * 16) + mf * 16 + g4) * PADB + koff;
                uint32_t a0 = *(const uint32_t*)ap;
                uint32_t a1 = *(const uint32_t*)(ap + 8 * PADB);
                uint32_t a2 = *(const uint32_t*)(ap + 16);
                uint32_t a3 = *(const uint32_t*)(ap + 8 * PADB + 16);
                #pragma unroll
                for (int nf = 0; nf < 4; nf++)
                    mma_e4m3(acc[mf][nf], a0, a1, a2, a3, bf[nf][0], bf[nf][1]);
            }
        }
        st++; if (st == STG) st = 0;
    }

    int c2 = 2 * q4;
    int rbase = m0 + wm * (MF * 16) + g4;
    #pragma unroll
    for (int mf = 0; mf < MF; mf++) {
        int r1 = rbase + mf * 16, r2 = r1 + 8;
        #pragma unroll
        for (int nf = 0; nf < 4; nf++) {
            int col = n0 + wn * 32 + nf * 8 + c2;
            if (do_exp) {
                float a00 = (acc[mf][nf][0] * alpha - EXP_SHIFT) * LOG2E;
                float a01 = (acc[mf][nf][1] * alpha - EXP_SHIFT) * LOG2E;
                float a10 = (acc[mf][nf][2] * alpha - EXP_SHIFT) * LOG2E;
                float a11 = (acc[mf][nf][3] * alpha - EXP_SHIFT) * LOG2E;
                __half2 h0 = __floats2half2_rn(a00, a01);
                __half2 h1 = __floats2half2_rn(a10, a11);
                uint32_t e0 = ex2_h2(*(uint32_t*)&h0);
                uint32_t e1 = ex2_h2(*(uint32_t*)&h1);
                *(uint16_t*)(C8 + (size_t)r1 * NC + col) = h2_to_e4m3x2(e0);
                *(uint16_t*)(C8 + (size_t)r2 * NC + col) = h2_to_e4m3x2(e1);
            } else {
                float b0 = 0.f, b1 = 0.f;
                if (bias) { b0 = bias[col]; b1 = bias[col + 1]; }
                float v00 = acc[mf][nf][0] * alpha + b0;
                float v01 = acc[mf][nf][1] * alpha + b1;
                float v10 = acc[mf][nf][2] * alpha + b0;
                float v11 = acc[mf][nf][3] * alpha + b1;
                if (C8) {
                    *(uint16_t*)(C8 + (size_t)r1 * NC + col) = pack_e4m3(v00, v01);
                    *(uint16_t*)(C8 + (size_t)r2 * NC + col) = pack_e4m3(v10, v11);
                } else {
                    *(float2*)(C32 + (size_t)r1 * NC + col) = make_float2(v00, v01);
                    *(float2*)(C32 + (size_t)r2 * NC + col) = make_float2(v10, v11);
                }
            }
        }
    }
}

#define GEMM_SMEM_4 (STAGES * (128 * PADH + 128 * PADH) * 2)   // 81920
#define GEMM_SMEM_2 (STAGES * (64 * PADH + 128 * PADH) * 2)    // 61440
#define F8_SMEM_4   (4 * (128 * PADB + 128 * PADB))            // 81920
#define F8_SMEM_2   (4 * (64 * PADB + 128 * PADB))             // 61440

// ---------------- reductions ----------------
__device__ __forceinline__ float blk_sum(float v, float* sm) {
    #pragma unroll
    for (int o = 16; o; o >>= 1) v += __shfl_xor_sync(0xffffffffu, v, o);
    int w = threadIdx.x >> 5;
    if ((threadIdx.x & 31) == 0) sm[w] = v;
    __syncthreads();
    if (threadIdx.x < 8) {
        float x = sm[threadIdx.x];
        #pragma unroll
        for (int o = 4; o; o >>= 1) x += __shfl_xor_sync(0xffu, x, o);
        if (threadIdx.x == 0) sm[0] = x;
    }
    __syncthreads();
    float r = sm[0];
    __syncthreads();
    return r;
}

// ---------------- elementwise kernels ----------------
__global__ void to_half_kernel(const float* __restrict__ in, __half* __restrict__ out, int n) {
    int i = blockIdx.x * 256 + threadIdx.x;
    if (i < n) out[i] = __float2half_rn(in[i]);
}

__global__ void to_f8_kernel(const float* __restrict__ in, uint8_t* __restrict__ out, int n) {
    int i = blockIdx.x * 256 + threadIdx.x;
    if (i < n) out[i] = (uint8_t)pack_e4m3(in[i], 0.0f);
}

__global__ void copy_both_kernel(const float* __restrict__ in, float* __restrict__ o32,
                                 __half* __restrict__ o16, int n) {
    int i = blockIdx.x * 256 + threadIdx.x;
    if (i < n) { float v = in[i]; o32[i] = v; o16[i] = __float2half_rn(v); }
}

__global__ void reduce_pv_kernel(const float* __restrict__ part, __half* __restrict__ out) {
    int i = blockIdx.x * 256 + threadIdx.x;
    float s = 0.0f;
    #pragma unroll
    for (int k = 0; k < PV_SPLIT; k++)
        s += part[(size_t)k * S_SLOTS * D_DIM + i];
    out[i] = __float2half_rn(s);
}

// LayerNorm fp32 -> fp16
__global__ void __launch_bounds__(256) ln_h_kernel(
    const float* __restrict__ x, const float* __restrict__ g,
    const float* __restrict__ be, __half* __restrict__ y)
{
    __shared__ float sm[8];
    int row = blockIdx.x;
    const float* xr = x + (size_t)row * D_DIM;
    int t = threadIdx.x;
    float v0 = xr[t], v1 = xr[t + 256], v2 = xr[t + 512];
    float s = blk_sum(v0 + v1 + v2, sm);
    float mean = s * (1.0f / 768.0f);
    float d0 = v0 - mean, d1 = v1 - mean, d2 = v2 - mean;
    float ss = blk_sum(d0 * d0 + d1 * d1 + d2 * d2, sm);
    float inv = rsqrtf(ss * (1.0f / 768.0f) + 1e-5f);
    __half* yr = y + (size_t)row * D_DIM;
    yr[t]       = __float2half_rn(d0 * inv * g[t]       + be[t]);
    yr[t + 256] = __float2half_rn(d1 * inv * g[t + 256] + be[t + 256]);
    yr[t + 512] = __float2half_rn(d2 * inv * g[t + 512] + be[t + 512]);
}

// LayerNorm fp32 -> e4m3
__global__ void __launch_bounds__(256) ln_8_kernel(
    const float* __restrict__ x, const float* __restrict__ g,
    const float* __restrict__ be, uint8_t* __restrict__ y)
{
    __shared__ float sm[8];
    int row = blockIdx.x;
    const float* xr = x + (size_t)row * D_DIM;
    int t = threadIdx.x;
    float v0 = xr[t], v1 = xr[t + 256], v2 = xr[t + 512];
    float s = blk_sum(v0 + v1 + v2, sm);
    float mean = s * (1.0f / 768.0f);
    float d0 = v0 - mean, d1 = v1 - mean, d2 = v2 - mean;
    float ss = blk_sum(d0 * d0 + d1 * d1 + d2 * d2, sm);
    float inv = rsqrtf(ss * (1.0f / 768.0f) + 1e-5f);
    uint8_t* yr = y + (size_t)row * D_DIM;
    yr[t]       = (uint8_t)pack_e4m3(d0 * inv * g[t]       + be[t], 0.0f);
    yr[t + 256] = (uint8_t)pack_e4m3(d1 * inv * g[t + 256] + be[t + 256], 0.0f);
    yr[t + 512] = (uint8_t)pack_e4m3(d2 * inv * g[t + 512] + be[t + 512], 0.0f);
}

// row sums of e4m3 P -> lsum (fp32)
__global__ void __launch_bounds__(256) rowsum8_kernel(
    const uint8_t* __restrict__ p, float* __restrict__ lsum)
{
    __shared__ float sm[8];
    int row = blockIdx.x;
    const uint32_t* pr = (const uint32_t*)(p + (size_t)row * N_IN);
    float s = 0.0f;
    #pragma unroll
    for (int i = 0; i < 16; i++) {
        uint32_t w = pr[threadIdx.x + i * 256];
        uint32_t f0 = e4m3x2_to_h2((uint16_t)(w & 0xFFFFu));
        uint32_t f1 = e4m3x2_to_h2((uint16_t)(w >> 16));
        float2 a = __half22float2(*(__half2*)&f0);
        float2 b = __half22float2(*(__half2*)&f1);
        s += (a.x + a.y) + (b.x + b.y);
    }
    s = blk_sum(s, sm);
    if (threadIdx.x == 0) lsum[row] = s;
}

// v8 [N_IN, D_DIM] e4m3 -> vT8 [D_DIM, N_IN] e4m3 (byte transpose)
__global__ void transpose_88(const uint8_t* __restrict__ in, uint8_t* __restrict__ out) {
    __shared__ uint8_t t[32][33];
    int c0 = blockIdx.x * 32, r0 = blockIdx.y * 32;
    for (int i = threadIdx.y; i < 32; i += 8)
        t[i][threadIdx.x] = in[(size_t)(r0 + i) * D_DIM + c0 + threadIdx.x];
    __syncthreads();
    for (int i = threadIdx.y; i < 32; i += 8)
        out[(size_t)(c0 + i) * N_IN + r0 + threadIdx.x] = t[threadIdx.x][i];
}

// fused GRU + LayerNorm(h): one block per row
__global__ void __launch_bounds__(256) gru_ln_kernel(
    const float* __restrict__ gx, const float* __restrict__ gh,
    const float* __restrict__ sp, float* __restrict__ hout,
    const float* __restrict__ g, const float* __restrict__ be,
    __half* __restrict__ y)
{
    __shared__ float sm[8];
    int row = blockIdx.x;
    int t = threadIdx.x;
    size_t b3 = (size_t)row * D3;
    size_t b1 = (size_t)row * D_DIM;
    float hv[3];
    #pragma unroll
    for (int j = 0; j < 3; j++) {
        int d = t + j * 256;
        float xr = gx[b3 + d], xz = gx[b3 + D_DIM + d], xn = gx[b3 + 2 * D_DIM + d];
        float hr = gh[b3 + d], hz = gh[b3 + D_DIM + d], hn = gh[b3 + 2 * D_DIM + d];
        float r = 0.5f + 0.5f * tanh_ap(0.5f * (xr + hr));
        float z = 0.5f + 0.5f * tanh_ap(0.5f * (xz + hz));
        float n = tanh_ap(xn + r * hn);
        hv[j] = (1.0f - z) * n + z * sp[b1 + d];
        hout[b1 + d] = hv[j];
    }
    float s = blk_sum(hv[0] + hv[1] + hv[2], sm);
    float mean = s * (1.0f / 768.0f);
    float d0 = hv[0] - mean, d1 = hv[1] - mean, d2 = hv[2] - mean;
    float ss = blk_sum(d0 * d0 + d1 * d1 + d2 * d2, sm);
    float inv = rsqrtf(ss * (1.0f / 768.0f) + 1e-5f);
    __half* yr = y + b1;
    yr[t]       = __float2half_rn(d0 * inv * g[t]       + be[t]);
    yr[t + 256] = __float2half_rn(d1 * inv * g[t + 256] + be[t + 256]);
    yr[t + 512] = __float2half_rn(d2 * inv * g[t + 512] + be[t + 512]);
}

// ---------------- host launch ----------------
static void launch_gemm4(const __half* A, const __half* B, float* C32, __half* C16,
                         uint8_t* C8, int M, int N, int K, float alpha,
                         const float* bias, const float* rowdiv, const float* addsrc,
                         int relu, cudaStream_t st = 0)
{
    dim3 g(N / BN, M / 128, 1);
    gemm_h<4><<<g, 256, GEMM_SMEM_4, st>>>(A, B, C32, C16, C8, K, K, N, alpha, bias,
                                           rowdiv, addsrc, relu);
}

static void launch_gemm2(const __half* A, const __half* B, float* C32, __half* C16,
                         uint8_t* C8, int M, int N, int K, float alpha,
                         const float* bias, const float* rowdiv, const float* addsrc,
                         int relu, cudaStream_t st = 0)
{
    dim3 g(N / BN, M / 64, 1);
    gemm_h<2><<<g, 256, GEMM_SMEM_2, st>>>(A, B, C32, C16, C8, K, K, N, alpha, bias,
                                           rowdiv, addsrc, relu);
}

extern "C" void kernel_launch(void* const* d_in, const int* in_sizes, int n_in,
                              void* d_out, int out_size)
{
    (void)in_sizes; (void)n_in; (void)out_size;
    const float* cand = (const float*)d_in[0];
    const float* pano = (const float*)d_in[1];
    const float* Wq   = (const float*)d_in[2];
    const float* bq   = (const float*)d_in[3];
    const float* Wk   = (const float*)d_in[4];
    const float* bk   = (const float*)d_in[5];
    const float* Wv   = (const float*)d_in[6];
    const float* bv   = (const float*)d_in[7];
    const float* Wih  = (const float*)d_in[8];
    const float* bih  = (const float*)d_in[9];
    const float* Whh  = (const float*)d_in[10];
    const float* bhh  = (const float*)d_in[11];
    const float* W1   = (const float*)d_in[12];
    const float* b1   = (const float*)d_in[13];
    const float* W2   = (const float*)d_in[14];
    const float* b2   = (const float*)d_in[15];
    const float* gin  = (const float*)d_in[16];
    const float* bein = (const float*)d_in[17];
    const float* gsl  = (const float*)d_in[18];
    const float* besl = (const float*)d_in[19];
    const float* gff  = (const float*)d_in[20];
    const float* beff = (const float*)d_in[21];

    cudaFuncSetAttribute(gemm_h<4>, cudaFuncAttributeMaxDynamicSharedMemorySize, GEMM_SMEM_4);
    cudaFuncSetAttribute(gemm_h<2>, cudaFuncAttributeMaxDynamicSharedMemorySize, GEMM_SMEM_2);
    cudaFuncSetAttribute(gemm_f8<4, 4>, cudaFuncAttributeMaxDynamicSharedMemorySize, F8_SMEM_4);
    cudaFuncSetAttribute(gemm_f8<2, 4>, cudaFuncAttributeMaxDynamicSharedMemorySize, F8_SMEM_2);

    float *pslots, *pl, *pgx, *pgh, *ph, *ppart;
    __half *pslots_h, *ptmp_h, *pupd_h, *pt_h;
    uint8_t *pln8, *pq8, *pk8, *pv8, *pp8, *pvT8, *wk8, *wv8;
    __half *wq, *w1, *w2, *wih, *whh;
    cudaGetSymbolAddress((void**)&pslots,  g_slots);
    cudaGetSymbolAddress((void**)&pl,      g_lsum);
    cudaGetSymbolAddress((void**)&pgx,     g_gx);
    cudaGetSymbolAddress((void**)&pgh,     g_gh);
    cudaGetSymbolAddress((void**)&ph,      g_h);
    cudaGetSymbolAddress((void**)&ppart,   g_pvpart);
    cudaGetSymbolAddress((void**)&pslots_h,g_slots_h);
    cudaGetSymbolAddress((void**)&ptmp_h,  g_tmp_h);
    cudaGetSymbolAddress((void**)&pupd_h,  g_upd_h);
    cudaGetSymbolAddress((void**)&pt_h,    g_t_h);
    cudaGetSymbolAddress((void**)&pln8,    g_pln8);
    cudaGetSymbolAddress((void**)&pq8,     g_q8);
    cudaGetSymbolAddress((void**)&pk8,     g_k8);
    cudaGetSymbolAddress((void**)&pv8,     g_v8);
    cudaGetSymbolAddress((void**)&pp8,     g_p8);
    cudaGetSymbolAddress((void**)&pvT8,    g_vT8);
    cudaGetSymbolAddress((void**)&wk8,     g_Wk8);
    cudaGetSymbolAddress((void**)&wv8,     g_Wv8);
    cudaGetSymbolAddress((void**)&wq,      g_Wq);
    cudaGetSymbolAddress((void**)&w1,      g_W1);
    cudaGetSymbolAddress((void**)&w2,      g_W2);
    cudaGetSymbolAddress((void**)&wih,     g_Wih);
    cudaGetSymbolAddress((void**)&whh,     g_Whh);

    const float scale = 1.0f / sqrtf((float)D_DIM);
    const int DD = D_DIM * D_DIM, D3D = D3 * D_DIM;

    cudaStream_t s2;
    cudaStreamCreateWithFlags(&s2, cudaStreamNonBlocking);
    cudaEvent_t evF[4], evJa[4], evJb[4];
    for (int i = 0; i < 4; i++) {
        cudaEventCreateWithFlags(&evF[i],  cudaEventDisableTiming);
        cudaEventCreateWithFlags(&evJa[i], cudaEventDisableTiming);
        cudaEventCreateWithFlags(&evJb[i], cudaEventDisableTiming);
    }

    // ---- setup: fp8 K/V projections ----
    to_f8_kernel<<<(DD + 255) / 256, 256>>>(Wk, wk8, DD);
    to_f8_kernel<<<(DD + 255) / 256, 256>>>(Wv, wv8, DD);
    ln_8_kernel<<<N_IN, 256>>>(pano, gin, bein, pln8);

    cudaEventRecord(evF[3], 0);
    cudaStreamWaitEvent(s2, evF[3], 0);
    to_half_kernel<<<(DD + 255) / 256, 256, 0, s2>>>(Wq, wq, DD);
    to_half_kernel<<<(DD + 255) / 256, 256, 0, s2>>>(W1, w1, DD);
    to_half_kernel<<<(DD + 255) / 256, 256, 0, s2>>>(W2, w2, DD);
    to_half_kernel<<<(D3D + 255) / 256, 256, 0, s2>>>(Wih, wih, D3D);
    to_half_kernel<<<(D3D + 255) / 256, 256, 0, s2>>>(Whh, whh, D3D);
    cudaEventRecord(evJa[3], s2);

    // kproj / vproj in fp8 -> e4m3 outputs
    {
        dim3 g(D_DIM / BN, N_IN / 128, 1);
        gemm_f8<4, 4><<<g, 256, F8_SMEM_4>>>(pln8, wk8, 0, pk8, D_DIM, D_DIM, D_DIM,
                                             1.0f, bk, 0);
        gemm_f8<4, 4><<<g, 256, F8_SMEM_4>>>(pln8, wv8, 0, pv8, D_DIM, D_DIM, D_DIM,
                                             1.0f, bv, 0);
    }
    transpose_88<<<dim3(D_DIM / 32, N_IN / 32), dim3(32, 8)>>>(pv8, pvT8);
    copy_both_kernel<<<(S_SLOTS * D_DIM) / 256, 256>>>(cand, pslots, pslots_h, S_SLOTS * D_DIM);
    cudaStreamWaitEvent(0, evJa[3], 0);

    for (int it = 0; it < 3; ++it) {
        // critical path: LN, qproj (-> e4m3), fp8 QK (+f16x2 exp -> e4m3 P)
        ln_h_kernel<<<S_SLOTS, 256>>>(pslots, gsl, besl, ptmp_h);
        launch_gemm2(ptmp_h, wq, 0, 0, pq8, S_SLOTS, D_DIM, D_DIM, 1.0f, bq, 0, 0, 0);
        {
            dim3 g(N_IN / BN, S_SLOTS / 128, 1);
            gemm_f8<4, 4><<<g, 256, F8_SMEM_4>>>(pq8, pk8, 0, pp8, D_DIM, D_DIM, N_IN,
                                                 scale, 0, 1);
        }

        // fork after QK: rowsum then gh on s2
        cudaEventRecord(evF[it], 0);
        cudaStreamWaitEvent(s2, evF[it], 0);
        rowsum8_kernel<<<S_SLOTS, 256, 0, s2>>>(pp8, pl);
        cudaEventRecord(evJa[it], s2);
        launch_gemm4(pslots_h, whh, pgh, 0, 0, S_SLOTS, D3, D_DIM, 1.0f, bhh, 0, 0, 0, s2);
        cudaEventRecord(evJb[it], s2);

        // P@V split-K in fp8, reduce -> upd_h
        {
            dim3 g(D_DIM / BN, S_SLOTS / 64, PV_SPLIT);
            gemm_f8<2, 4><<<g, 256, F8_SMEM_2>>>(pp8, pvT8, ppart, 0, PV_KSPLIT, N_IN,
                                                 D_DIM, 1.0f, 0, 0);
        }
        reduce_pv_kernel<<<(S_SLOTS * D_DIM) / 256, 256>>>(ppart, pupd_h);

        // gx = (upd_raw @ Wih^T)/lsum + bih
        cudaStreamWaitEvent(0, evJa[it], 0);
        launch_gemm4(pupd_h, wih, pgx, 0, 0, S_SLOTS, D3, D_DIM, 1.0f, bih, pl, 0, 0);

        // fused GRU + ff-LN (needs gh)
        cudaStreamWaitEvent(0, evJb[it], 0);
        gru_ln_kernel<<<S_SLOTS, 256>>>(pgx, pgh, pslots, ph, gff, beff, ptmp_h);

        // slots = h + relu(LN(h) @ W1^T + b1) @ W2^T + b2
        launch_gemm2(ptmp_h, w1, 0, pt_h, 0, S_SLOTS, D_DIM, D_DIM, 1.0f, b1, 0, 0, 1);
        if (it == 2) {
            launch_gemm2(pt_h, w2, (float*)d_out, 0, 0, S_SLOTS, D_DIM, D_DIM, 1.0f, b2, 0, ph, 0);
        } else {
            launch_gemm2(pt_h, w2, pslots, pslots_h, 0, S_SLOTS, D_DIM, D_DIM, 1.0f, b2, 0, ph, 0);
        }
    }
}

// round 17
// speedup vs baseline: 1.0588x; 1.0341x over previous
#include <cuda_runtime.h>
#include <cuda_fp16.h>
#include <math.h>
#include <stdint.h>

// ---------------- problem constants ----------------
#define S_SLOTS 4096
#define N_IN    16384
#define D_DIM   768
#define D3      2304
#define PV_SPLIT 8
#define PV_KSPLIT (N_IN / PV_SPLIT)   // 2048

#define BN 128
#define BKH 32                  // halves per k-stage (fp16 GEMM)
#define PADH 40                 // halves per smem row
#define PADB 80                 // bytes per smem row (fp8 GEMM)
#define STAGES 4
#define BTILE_H (128 * PADH)

#define EXP_SHIFT 2.0f
#define LOG2E 1.44269504f

// ---------------- scratch (device globals) ----------------
__device__ float g_slots [S_SLOTS * D_DIM];
__device__ float g_lsum  [S_SLOTS];
__device__ float g_gx    [S_SLOTS * D3];
__device__ float g_gh    [S_SLOTS * D3];
__device__ float g_h     [S_SLOTS * D_DIM];
__device__ __half g_pvpart[(size_t)PV_SPLIT * S_SLOTS * D_DIM];  // fp16 partials
__device__ __half g_pln_h  [N_IN * D_DIM];
__device__ __half g_v_h    [N_IN * D_DIM];
__device__ __half g_slots_h[S_SLOTS * D_DIM];
__device__ __half g_tmp_h  [S_SLOTS * D_DIM];
__device__ __half g_upd_h  [S_SLOTS * D_DIM];
__device__ __half g_t_h    [S_SLOTS * D_DIM];
__device__ uint8_t g_q8  [S_SLOTS * D_DIM];          // q (e4m3)
__device__ uint8_t g_k8  [N_IN * D_DIM];             // k (e4m3)
__device__ uint8_t g_p8  [(size_t)S_SLOTS * N_IN];   // P (e4m3)
__device__ uint8_t g_vT8 [(size_t)D_DIM * N_IN];     // v^T (e4m3)
__device__ __half g_Wq [D_DIM * D_DIM];
__device__ __half g_Wk [D_DIM * D_DIM];
__device__ __half g_Wv [D_DIM * D_DIM];
__device__ __half g_W1 [D_DIM * D_DIM];
__device__ __half g_W2 [D_DIM * D_DIM];
__device__ __half g_Wih[D3 * D_DIM];
__device__ __half g_Whh[D3 * D_DIM];

// ---------------- PTX helpers ----------------
__device__ __forceinline__ uint32_t s2u(const void* p) {
    uint32_t a;
    asm("{ .reg .u64 t; cvta.to.shared.u64 t, %1; cvt.u32.u64 %0, t; }" : "=r"(a) : "l"(p));
    return a;
}

__device__ __forceinline__ void cp16(uint32_t s, const void* g) {
    asm volatile("cp.async.cg.shared.global [%0], [%1], 16;" :: "r"(s), "l"(g) : "memory");
}

__device__ __forceinline__ uint32_t ex2_h2(uint32_t x) {
    uint32_t y;
    asm("ex2.approx.f16x2 %0, %1;" : "=r"(y) : "r"(x));
    return y;
}

__device__ __forceinline__ float tanh_ap(float x) {
    float y;
    asm("tanh.approx.f32 %0, %1;" : "=f"(y) : "f"(x));
    return y;
}

__device__ __forceinline__ uint16_t pack_e4m3(float lo, float hi) {
    uint16_t r;
    asm("cvt.rn.satfinite.e4m3x2.f32 %0, %1, %2;" : "=h"(r) : "f"(hi), "f"(lo));
    return r;
}

__device__ __forceinline__ uint16_t h2_to_e4m3x2(uint32_t h2) {
    uint16_t r;
    asm("cvt.rn.satfinite.e4m3x2.f16x2 %0, %1;" : "=h"(r) : "r"(h2));
    return r;
}

__device__ __forceinline__ uint32_t e4m3x2_to_h2(uint16_t v) {
    uint32_t r;
    asm("cvt.rn.f16x2.e4m3x2 %0, %1;" : "=r"(r) : "h"(v));
    return r;
}

__device__ __forceinline__ void ldm_x4(uint32_t& r0, uint32_t& r1, uint32_t& r2,
                                       uint32_t& r3, uint32_t a) {
    asm volatile("ldmatrix.sync.aligned.m8n8.x4.shared.b16 {%0,%1,%2,%3}, [%4];"
                 : "=r"(r0), "=r"(r1), "=r"(r2), "=r"(r3) : "r"(a));
}

__device__ __forceinline__ void mma_f16(float* c, uint32_t a0, uint32_t a1,
                                        uint32_t a2, uint32_t a3,
                                        uint32_t b0, uint32_t b1) {
    asm volatile(
        "mma.sync.aligned.m16n8k16.row.col.f32.f16.f16.f32 "
        "{%0,%1,%2,%3}, {%4,%5,%6,%7}, {%8,%9}, {%0,%1,%2,%3};"
        : "+f"(c[0]), "+f"(c[1]), "+f"(c[2]), "+f"(c[3])
        : "r"(a0), "r"(a1), "r"(a2), "r"(a3), "r"(b0), "r"(b1));
}

__device__ __forceinline__ void mma_e4m3(float* c, uint32_t a0, uint32_t a1,
                                         uint32_t a2, uint32_t a3,
                                         uint32_t b0, uint32_t b1) {
    asm volatile(
        "mma.sync.aligned.m16n8k32.row.col.f32.e4m3.e4m3.f32 "
        "{%0,%1,%2,%3}, {%4,%5,%6,%7}, {%8,%9}, {%0,%1,%2,%3};"
        : "+f"(c[0]), "+f"(c[1]), "+f"(c[2]), "+f"(c[3])
        : "r"(a0), "r"(a1), "r"(a2), "r"(a3), "r"(b0), "r"(b1));
}

// ---------------- fp16 tensor-core NT GEMM (templated M-tile) ----------------
template <int MF>
__global__ void __launch_bounds__(256, MF == 4 ? 2 : 3) gemm_h(
    const __half* __restrict__ A, const __half* __restrict__ B,
    float* __restrict__ C32, __half* __restrict__ C16, uint8_t* __restrict__ C8,
    int K, int ldab, int NC, float alpha,
    const float* __restrict__ bias, const float* __restrict__ rowdiv,
    const float* __restrict__ addsrc, int relu)
{
    constexpr int TBM = MF * 32;
    constexpr int ATILE_H = TBM * PADH;
    extern __shared__ __half smh[];
    __half* As = smh;
    __half* Bs = smh + STAGES * ATILE_H;

    int tid = threadIdx.x, lane = tid & 31, wid = tid >> 5;
    int wm = wid & 1, wn = wid >> 1;
    int m0 = blockIdx.y * TBM, n0 = blockIdx.x * BN;
    int KT = K / BKH;

    int lr = tid >> 2;
    int cch = tid & 3;
    const __half* Ag = A + (size_t)(m0 + lr) * ldab + cch * 8;
    const __half* Bg = B + (size_t)(n0 + lr) * ldab + cch * 8;
    uint32_t as_u = s2u(As), bs_u = s2u(Bs);

    uint32_t a_off[MF], b_off[2];
    {
        int ar = (lane & 7) + 8 * ((lane >> 3) & 1);
        int ak = 8 * (lane >> 4);
        #pragma unroll
        for (int mf = 0; mf < MF; mf++)
            a_off[mf] = (uint32_t)((wm * (MF * 16) + mf * 16 + ar) * PADH + ak) * 2u;
        #pragma unroll
        for (int p = 0; p < 2; p++)
            b_off[p] = (uint32_t)((wn * 32 + p * 16 + ar) * PADH + ak) * 2u;
    }

    float acc[MF][4][4];
    #pragma unroll
    for (int i = 0; i < MF; i++)
        #pragma unroll
        for (int j = 0; j < 4; j++)
            #pragma unroll
            for (int q = 0; q < 4; q++) acc[i][j][q] = 0.0f;

    #pragma unroll
    for (int p = 0; p < 3; p++) {
        #pragma unroll
        for (int i = 0; i < MF / 2; i++) {
            uint32_t soff = (uint32_t)(p * ATILE_H + (lr + i * 64) * PADH) * 2u + cch * 16u;
            cp16(as_u + soff, Ag + (size_t)i * 64 * ldab + (size_t)p * BKH);
        }
        #pragma unroll
        for (int i = 0; i < 2; i++) {
            uint32_t soff = (uint32_t)(p * BTILE_H + (lr + i * 64) * PADH) * 2u + cch * 16u;
            cp16(bs_u + soff, Bg + (size_t)i * 64 * ldab + (size_t)p * BKH);
        }
        asm volatile("cp.async.commit_group;" ::: "memory");
    }

    for (int kt = 0; kt < KT; kt++) {
        asm volatile("cp.async.wait_group 2;" ::: "memory");
        __syncthreads();
        int st = kt & (STAGES - 1);
        if (kt + 3 < KT) {
            int d = (kt + 3) & (STAGES - 1);
            #pragma unroll
            for (int i = 0; i < MF / 2; i++) {
                uint32_t soff = (uint32_t)(d * ATILE_H + (lr + i * 64) * PADH) * 2u + cch * 16u;
                cp16(as_u + soff, Ag + (size_t)i * 64 * ldab + (size_t)(kt + 3) * BKH);
            }
            #pragma unroll
            for (int i = 0; i < 2; i++) {
                uint32_t soff = (uint32_t)(d * BTILE_H + (lr + i * 64) * PADH) * 2u + cch * 16u;
                cp16(bs_u + soff, Bg + (size_t)i * 64 * ldab + (size_t)(kt + 3) * BKH);
            }
        }
        asm volatile("cp.async.commit_group;" ::: "memory");

        uint32_t abase = as_u + (uint32_t)(st * ATILE_H) * 2u;
        uint32_t bbase = bs_u + (uint32_t)(st * BTILE_H) * 2u;

        #pragma unroll
        for (int ks = 0; ks < 2; ks++) {
            uint32_t koff = ks * 32u;
            uint32_t bf[4][2];
            #pragma unroll
            for (int p = 0; p < 2; p++) {
                uint32_t r0, r1, r2, r3;
                ldm_x4(r0, r1, r2, r3, bbase + b_off[p] + koff);
                bf[2 * p][0] = r0; bf[2 * p + 1][0] = r1;
                bf[2 * p][1] = r2; bf[2 * p + 1][1] = r3;
            }
            #pragma unroll
            for (int mf = 0; mf < MF; mf++) {
                uint32_t a0, a1, a2, a3;
                ldm_x4(a0, a1, a2, a3, abase + a_off[mf] + koff);
                #pragma unroll
                for (int nf = 0; nf < 4; nf++)
                    mma_f16(acc[mf][nf], a0, a1, a2, a3, bf[nf][0], bf[nf][1]);
            }
        }
    }

    // -------- epilogue --------
    int g4 = lane >> 2, q4 = lane & 3;
    int c2 = 2 * q4;
    int rbase = m0 + wm * (MF * 16) + g4;
    #pragma unroll
    for (int mf = 0; mf < MF; mf++) {
        int r1 = rbase + mf * 16;
        int r2 = r1 + 8;
        float inv1 = 1.0f, inv2 = 1.0f;
        if (rowdiv) { inv1 = 1.0f / rowdiv[r1]; inv2 = 1.0f / rowdiv[r2]; }
        #pragma unroll
        for (int nf = 0; nf < 4; nf++) {
            int col = n0 + wn * 32 + nf * 8 + c2;
            float b0 = 0.f, b1 = 0.f;
            if (bias) { b0 = bias[col]; b1 = bias[col + 1]; }
            float v00 = acc[mf][nf][0] * alpha * inv1 + b0;
            float v01 = acc[mf][nf][1] * alpha * inv1 + b1;
            float v10 = acc[mf][nf][2] * alpha * inv2 + b0;
            float v11 = acc[mf][nf][3] * alpha * inv2 + b1;
            if (relu) {
                v00 = fmaxf(v00, 0.f); v01 = fmaxf(v01, 0.f);
                v10 = fmaxf(v10, 0.f); v11 = fmaxf(v11, 0.f);
            }
            if (addsrc) {
                const float* s1 = addsrc + (size_t)r1 * NC + col;
                const float* s2 = addsrc + (size_t)r2 * NC + col;
                v00 += s1[0]; v01 += s1[1]; v10 += s2[0]; v11 += s2[1];
            }
            if (C32) {
                *(float2*)(C32 + (size_t)r1 * NC + col) = make_float2(v00, v01);
                *(float2*)(C32 + (size_t)r2 * NC + col) = make_float2(v10, v11);
            }
            if (C16) {
                *(__half2*)(C16 + (size_t)r1 * NC + col) = __floats2half2_rn(v00, v01);
                *(__half2*)(C16 + (size_t)r2 * NC + col) = __floats2half2_rn(v10, v11);
            }
            if (C8) {
                *(uint16_t*)(C8 + (size_t)r1 * NC + col) = pack_e4m3(v00, v01);
                *(uint16_t*)(C8 + (size_t)r2 * NC + col) = pack_e4m3(v10, v11);
            }
        }
    }
}

// ---------------- fp8 e4m3 NT GEMM (templated M-tile) ----------
// do_exp: P = exp(acc*alpha - SHIFT) via f16x2 MUFU, stored e4m3 to C8.
// else:   fp16 partials to C16 (+ blockIdx.z slab for split-K).
template <int MF>
__global__ void __launch_bounds__(256, MF == 4 ? 2 : 3) gemm_f8(
    const uint8_t* __restrict__ A, const uint8_t* __restrict__ B,
    __half* __restrict__ C16, uint8_t* __restrict__ C8,
    int K, int ldab, int NC, float alpha, int do_exp)
{
    constexpr int TBM = MF * 32;
    constexpr int ASTG = TBM * PADB;
    constexpr int BSTG = 128 * PADB;
    extern __shared__ uint8_t smb[];
    uint8_t* As = smb;
    uint8_t* Bs = smb + STAGES * ASTG;

    int tid = threadIdx.x, lane = tid & 31, wid = tid >> 5;
    int wm = wid & 1, wn = wid >> 1;
    int m0 = blockIdx.y * TBM, n0 = blockIdx.x * BN;
    int sk = blockIdx.z;
    int KT = K / 64;

    int lr = tid >> 2;
    int cch = tid & 3;
    const uint8_t* Ag = A + (size_t)(m0 + lr) * ldab + (size_t)sk * K + cch * 16;
    const uint8_t* Bg = B + (size_t)(n0 + lr) * ldab + (size_t)sk * K + cch * 16;
    uint32_t as_u = s2u(As), bs_u = s2u(Bs);

    if (C16 && !do_exp) C16 += (size_t)sk * (size_t)(gridDim.y * TBM) * NC;

    int g4 = lane >> 2, q4 = lane & 3;

    float acc[MF][4][4];
    #pragma unroll
    for (int i = 0; i < MF; i++)
        #pragma unroll
        for (int j = 0; j < 4; j++)
            #pragma unroll
            for (int q = 0; q < 4; q++) acc[i][j][q] = 0.0f;

    #pragma unroll
    for (int p = 0; p < 3; p++) {
        #pragma unroll
        for (int i = 0; i < MF / 2; i++)
            cp16(as_u + (uint32_t)(p * ASTG + (lr + i * 64) * PADB) + cch * 16u,
                 Ag + (size_t)i * 64 * ldab + (size_t)p * 64);
        #pragma unroll
        for (int i = 0; i < 2; i++)
            cp16(bs_u + (uint32_t)(p * BSTG + (lr + i * 64) * PADB) + cch * 16u,
                 Bg + (size_t)i * 64 * ldab + (size_t)p * 64);
        asm volatile("cp.async.commit_group;" ::: "memory");
    }

    for (int kt = 0; kt < KT; kt++) {
        asm volatile("cp.async.wait_group 2;" ::: "memory");
        __syncthreads();
        int st = kt & (STAGES - 1);
        if (kt + 3 < KT) {
            int d = (kt + 3) & (STAGES - 1);
            #pragma unroll
            for (int i = 0; i < MF / 2; i++)
                cp16(as_u + (uint32_t)(d * ASTG + (lr + i * 64) * PADB) + cch * 16u,
                     Ag + (size_t)i * 64 * ldab + (size_t)(kt + 3) * 64);
            #pragma unroll
            for (int i = 0; i < 2; i++)
                cp16(bs_u + (uint32_t)(d * BSTG + (lr + i * 64) * PADB) + cch * 16u,
                     Bg + (size_t)i * 64 * ldab + (size_t)(kt + 3) * 64);
        }
        asm volatile("cp.async.commit_group;" ::: "memory");

        const uint8_t* ab = As + st * ASTG;
        const uint8_t* bb = Bs + st * BSTG;

        #pragma unroll
        for (int ks = 0; ks < 2; ks++) {
            int koff = ks * 32 + q4 * 4;
            uint32_t bf[4][2];
            #pragma unroll
            for (int nf = 0; nf < 4; nf++) {
                const uint8_t* bp = bb + (wn * 32 + nf * 8 + g4) * PADB + koff;
                bf[nf][0] = *(const uint32_t*)bp;
                bf[nf][1] = *(const uint32_t*)(bp + 16);
            }
            #pragma unroll
            for (int mf = 0; mf < MF; mf++) {
                const uint8_t* ap = ab + (wm * (MF * 16) + mf * 16 + g4) * PADB + koff;
                uint32_t a0 = *(const uint32_t*)ap;
                uint32_t a1 = *(const uint32_t*)(ap + 8 * PADB);
                uint32_t a2 = *(const uint32_t*)(ap + 16);
                uint32_t a3 = *(const uint32_t*)(ap + 8 * PADB + 16);
                #pragma unroll
                for (int nf = 0; nf < 4; nf++)
                    mma_e4m3(acc[mf][nf], a0, a1, a2, a3, bf[nf][0], bf[nf][1]);
            }
        }
    }

    int c2 = 2 * q4;
    int rbase = m0 + wm * (MF * 16) + g4;
    #pragma unroll
    for (int mf = 0; mf < MF; mf++) {
        int r1 = rbase + mf * 16, r2 = r1 + 8;
        #pragma unroll
        for (int nf = 0; nf < 4; nf++) {
            int col = n0 + wn * 32 + nf * 8 + c2;
            if (do_exp) {
                float a00 = (acc[mf][nf][0] * alpha - EXP_SHIFT) * LOG2E;
                float a01 = (acc[mf][nf][1] * alpha - EXP_SHIFT) * LOG2E;
                float a10 = (acc[mf][nf][2] * alpha - EXP_SHIFT) * LOG2E;
                float a11 = (acc[mf][nf][3] * alpha - EXP_SHIFT) * LOG2E;
                __half2 h0 = __floats2half2_rn(a00, a01);
                __half2 h1 = __floats2half2_rn(a10, a11);
                uint32_t e0 = ex2_h2(*(uint32_t*)&h0);
                uint32_t e1 = ex2_h2(*(uint32_t*)&h1);
                *(uint16_t*)(C8 + (size_t)r1 * NC + col) = h2_to_e4m3x2(e0);
                *(uint16_t*)(C8 + (size_t)r2 * NC + col) = h2_to_e4m3x2(e1);
            } else {
                *(__half2*)(C16 + (size_t)r1 * NC + col) =
                    __floats2half2_rn(acc[mf][nf][0], acc[mf][nf][1]);
                *(__half2*)(C16 + (size_t)r2 * NC + col) =
                    __floats2half2_rn(acc[mf][nf][2], acc[mf][nf][3]);
            }
        }
    }
}

#define GEMM_SMEM_4 (STAGES * (128 * PADH + 128 * PADH) * 2)   // 81920
#define GEMM_SMEM_2 (STAGES * (64 * PADH + 128 * PADH) * 2)    // 61440
#define F8_SMEM_4   (STAGES * (128 * PADB + 128 * PADB))       // 81920
#define F8_SMEM_2   (STAGES * (64 * PADB + 128 * PADB))        // 61440

// ---------------- reductions ----------------
__device__ __forceinline__ float blk_sum(float v, float* sm) {
    #pragma unroll
    for (int o = 16; o; o >>= 1) v += __shfl_xor_sync(0xffffffffu, v, o);
    int w = threadIdx.x >> 5;
    if ((threadIdx.x & 31) == 0) sm[w] = v;
    __syncthreads();
    if (threadIdx.x < 8) {
        float x = sm[threadIdx.x];
        #pragma unroll
        for (int o = 4; o; o >>= 1) x += __shfl_xor_sync(0xffu, x, o);
        if (threadIdx.x == 0) sm[0] = x;
    }
    __syncthreads();
    float r = sm[0];
    __syncthreads();
    return r;
}

// ---------------- elementwise kernels ----------------
__global__ void to_half_kernel(const float* __restrict__ in, __half* __restrict__ out, int n) {
    int i = blockIdx.x * 256 + threadIdx.x;
    if (i < n) out[i] = __float2half_rn(in[i]);
}

__global__ void copy_both_kernel(const float* __restrict__ in, float* __restrict__ o32,
                                 __half* __restrict__ o16, int n) {
    int i = blockIdx.x * 256 + threadIdx.x;
    if (i < n) { float v = in[i]; o32[i] = v; o16[i] = __float2half_rn(v); }
}

// sum PV_SPLIT fp16 partial slabs (half2-vectorized) -> fp16 upd
__global__ void reduce_pv_kernel(const __half* __restrict__ part, __half* __restrict__ out) {
    int i = blockIdx.x * 256 + threadIdx.x;   // over (S_SLOTS*D_DIM)/2
    const __half2* p2 = (const __half2*)part;
    float sx = 0.0f, sy = 0.0f;
    #pragma unroll
    for (int k = 0; k < PV_SPLIT; k++) {
        float2 v = __half22float2(p2[(size_t)k * (S_SLOTS * D_DIM / 2) + i]);
        sx += v.x; sy += v.y;
    }
    ((__half2*)out)[i] = __floats2half2_rn(sx, sy);
}

// LayerNorm fp32 -> fp16
__global__ void __launch_bounds__(256) ln_h_kernel(
    const float* __restrict__ x, const float* __restrict__ g,
    const float* __restrict__ be, __half* __restrict__ y)
{
    __shared__ float sm[8];
    int row = blockIdx.x;
    const float* xr = x + (size_t)row * D_DIM;
    int t = threadIdx.x;
    float v0 = xr[t], v1 = xr[t + 256], v2 = xr[t + 512];
    float s = blk_sum(v0 + v1 + v2, sm);
    float mean = s * (1.0f / 768.0f);
    float d0 = v0 - mean, d1 = v1 - mean, d2 = v2 - mean;
    float ss = blk_sum(d0 * d0 + d1 * d1 + d2 * d2, sm);
    float inv = rsqrtf(ss * (1.0f / 768.0f) + 1e-5f);
    __half* yr = y + (size_t)row * D_DIM;
    yr[t]       = __float2half_rn(d0 * inv * g[t]       + be[t]);
    yr[t + 256] = __float2half_rn(d1 * inv * g[t + 256] + be[t + 256]);
    yr[t + 512] = __float2half_rn(d2 * inv * g[t + 512] + be[t + 512]);
}

// row sums of e4m3 P -> lsum (fp32)
__global__ void __launch_bounds__(256) rowsum8_kernel(
    const uint8_t* __restrict__ p, float* __restrict__ lsum)
{
    __shared__ float sm[8];
    int row = blockIdx.x;
    const uint32_t* pr = (const uint32_t*)(p + (size_t)row * N_IN);
    float s = 0.0f;
    #pragma unroll
    for (int i = 0; i < 16; i++) {
        uint32_t w = pr[threadIdx.x + i * 256];
        uint32_t f0 = e4m3x2_to_h2((uint16_t)(w & 0xFFFFu));
        uint32_t f1 = e4m3x2_to_h2((uint16_t)(w >> 16));
        float2 a = __half22float2(*(__half2*)&f0);
        float2 b = __half22float2(*(__half2*)&f1);
        s += (a.x + a.y) + (b.x + b.y);
    }
    s = blk_sum(s, sm);
    if (threadIdx.x == 0) lsum[row] = s;
}

// v_h [N_IN, D_DIM] fp16 -> vT8 [D_DIM, N_IN] e4m3
__global__ void transpose_8(const __half* __restrict__ in, uint8_t* __restrict__ out) {
    __shared__ __half t[32][33];
    int c0 = blockIdx.x * 32, r0 = blockIdx.y * 32;
    for (int i = threadIdx.y; i < 32; i += 8)
        t[i][threadIdx.x] = in[(size_t)(r0 + i) * D_DIM + c0 + threadIdx.x];
    __syncthreads();
    for (int i = threadIdx.y; i < 32; i += 8) {
        float f = __half2float(t[threadIdx.x][i]);
        out[(size_t)(c0 + i) * N_IN + r0 + threadIdx.x] = (uint8_t)pack_e4m3(f, 0.0f);
    }
}

// fused GRU + LayerNorm(h): one block per row
__global__ void __launch_bounds__(256) gru_ln_kernel(
    const float* __restrict__ gx, const float* __restrict__ gh,
    const float* __restrict__ sp, float* __restrict__ hout,
    const float* __restrict__ g, const float* __restrict__ be,
    __half* __restrict__ y)
{
    __shared__ float sm[8];
    int row = blockIdx.x;
    int t = threadIdx.x;
    size_t b3 = (size_t)row * D3;
    size_t b1 = (size_t)row * D_DIM;
    float hv[3];
    #pragma unroll
    for (int j = 0; j < 3; j++) {
        int d = t + j * 256;
        float xr = gx[b3 + d], xz = gx[b3 + D_DIM + d], xn = gx[b3 + 2 * D_DIM + d];
        float hr = gh[b3 + d], hz = gh[b3 + D_DIM + d], hn = gh[b3 + 2 * D_DIM + d];
        float r = 0.5f + 0.5f * tanh_ap(0.5f * (xr + hr));
        float z = 0.5f + 0.5f * tanh_ap(0.5f * (xz + hz));
        float n = tanh_ap(xn + r * hn);
        hv[j] = (1.0f - z) * n + z * sp[b1 + d];
        hout[b1 + d] = hv[j];
    }
    float s = blk_sum(hv[0] + hv[1] + hv[2], sm);
    float mean = s * (1.0f / 768.0f);
    float d0 = hv[0] - mean, d1 = hv[1] - mean, d2 = hv[2] - mean;
    float ss = blk_sum(d0 * d0 + d1 * d1 + d2 * d2, sm);
    float inv = rsqrtf(ss * (1.0f / 768.0f) + 1e-5f);
    __half* yr = y + b1;
    yr[t]       = __float2half_rn(d0 * inv * g[t]       + be[t]);
    yr[t + 256] = __float2half_rn(d1 * inv * g[t + 256] + be[t + 256]);
    yr[t + 512] = __float2half_rn(d2 * inv * g[t + 512] + be[t + 512]);
}

// ---------------- host launch ----------------
static void launch_gemm4(const __half* A, const __half* B, float* C32, __half* C16,
                         uint8_t* C8, int M, int N, int K, float alpha,
                         const float* bias, const float* rowdiv, const float* addsrc,
                         int relu, cudaStream_t st = 0)
{
    dim3 g(N / BN, M / 128, 1);
    gemm_h<4><<<g, 256, GEMM_SMEM_4, st>>>(A, B, C32, C16, C8, K, K, N, alpha, bias,
                                           rowdiv, addsrc, relu);
}

static void launch_gemm2(const __half* A, const __half* B, float* C32, __half* C16,
                         uint8_t* C8, int M, int N, int K, float alpha,
                         const float* bias, const float* rowdiv, const float* addsrc,
                         int relu, cudaStream_t st = 0)
{
    dim3 g(N / BN, M / 64, 1);
    gemm_h<2><<<g, 256, GEMM_SMEM_2, st>>>(A, B, C32, C16, C8, K, K, N, alpha, bias,
                                           rowdiv, addsrc, relu);
}

extern "C" void kernel_launch(void* const* d_in, const int* in_sizes, int n_in,
                              void* d_out, int out_size)
{
    (void)in_sizes; (void)n_in; (void)out_size;
    const float* cand = (const float*)d_in[0];
    const float* pano = (const float*)d_in[1];
    const float* Wq   = (const float*)d_in[2];
    const float* bq   = (const float*)d_in[3];
    const float* Wk   = (const float*)d_in[4];
    const float* bk   = (const float*)d_in[5];
    const float* Wv   = (const float*)d_in[6];
    const float* bv   = (const float*)d_in[7];
    const float* Wih  = (const float*)d_in[8];
    const float* bih  = (const float*)d_in[9];
    const float* Whh  = (const float*)d_in[10];
    const float* bhh  = (const float*)d_in[11];
    const float* W1   = (const float*)d_in[12];
    const float* b1   = (const float*)d_in[13];
    const float* W2   = (const float*)d_in[14];
    const float* b2   = (const float*)d_in[15];
    const float* gin  = (const float*)d_in[16];
    const float* bein = (const float*)d_in[17];
    const float* gsl  = (const float*)d_in[18];
    const float* besl = (const float*)d_in[19];
    const float* gff  = (const float*)d_in[20];
    const float* beff = (const float*)d_in[21];

    cudaFuncSetAttribute(gemm_h<4>, cudaFuncAttributeMaxDynamicSharedMemorySize, GEMM_SMEM_4);
    cudaFuncSetAttribute(gemm_h<2>, cudaFuncAttributeMaxDynamicSharedMemorySize, GEMM_SMEM_2);
    cudaFuncSetAttribute(gemm_f8<4>, cudaFuncAttributeMaxDynamicSharedMemorySize, F8_SMEM_4);
    cudaFuncSetAttribute(gemm_f8<2>, cudaFuncAttributeMaxDynamicSharedMemorySize, F8_SMEM_2);

    float *pslots, *pl, *pgx, *pgh, *ph;
    __half *ppart, *pln_h, *pv_h, *pslots_h, *ptmp_h, *pupd_h, *pt_h;
    uint8_t *pq8, *pk8, *pp8, *pvT8;
    __half *wq, *wk, *wv, *w1, *w2, *wih, *whh;
    cudaGetSymbolAddress((void**)&pslots,  g_slots);
    cudaGetSymbolAddress((void**)&pl,      g_lsum);
    cudaGetSymbolAddress((void**)&pgx,     g_gx);
    cudaGetSymbolAddress((void**)&pgh,     g_gh);
    cudaGetSymbolAddress((void**)&ph,      g_h);
    cudaGetSymbolAddress((void**)&ppart,   g_pvpart);
    cudaGetSymbolAddress((void**)&pln_h,   g_pln_h);
    cudaGetSymbolAddress((void**)&pv_h,    g_v_h);
    cudaGetSymbolAddress((void**)&pslots_h,g_slots_h);
    cudaGetSymbolAddress((void**)&ptmp_h,  g_tmp_h);
    cudaGetSymbolAddress((void**)&pupd_h,  g_upd_h);
    cudaGetSymbolAddress((void**)&pt_h,    g_t_h);
    cudaGetSymbolAddress((void**)&pq8,     g_q8);
    cudaGetSymbolAddress((void**)&pk8,     g_k8);
    cudaGetSymbolAddress((void**)&pp8,     g_p8);
    cudaGetSymbolAddress((void**)&pvT8,    g_vT8);
    cudaGetSymbolAddress((void**)&wq,      g_Wq);
    cudaGetSymbolAddress((void**)&wk,      g_Wk);
    cudaGetSymbolAddress((void**)&wv,      g_Wv);
    cudaGetSymbolAddress((void**)&w1,      g_W1);
    cudaGetSymbolAddress((void**)&w2,      g_W2);
    cudaGetSymbolAddress((void**)&wih,     g_Wih);
    cudaGetSymbolAddress((void**)&whh,     g_Whh);

    const float scale = 1.0f / sqrtf((float)D_DIM);
    const int DD = D_DIM * D_DIM, D3D = D3 * D_DIM;

    cudaStream_t s2;
    cudaStreamCreateWithFlags(&s2, cudaStreamNonBlocking);
    cudaEvent_t evF[4], evJa[4], evJb[4];
    for (int i = 0; i < 4; i++) {
        cudaEventCreateWithFlags(&evF[i],  cudaEventDisableTiming);
        cudaEventCreateWithFlags(&evJa[i], cudaEventDisableTiming);
        cudaEventCreateWithFlags(&evJb[i], cudaEventDisableTiming);
    }

    // ---- setup ----
    to_half_kernel<<<(DD + 255) / 256, 256>>>(Wk, wk, DD);
    to_half_kernel<<<(DD + 255) / 256, 256>>>(Wv, wv, DD);
    ln_h_kernel<<<N_IN, 256>>>(pano, gin, bein, pln_h);

    cudaEventRecord(evF[3], 0);
    cudaStreamWaitEvent(s2, evF[3], 0);
    to_half_kernel<<<(DD + 255) / 256, 256, 0, s2>>>(Wq, wq, DD);
    to_half_kernel<<<(DD + 255) / 256, 256, 0, s2>>>(W1, w1, DD);
    to_half_kernel<<<(DD + 255) / 256, 256, 0, s2>>>(W2, w2, DD);
    to_half_kernel<<<(D3D + 255) / 256, 256, 0, s2>>>(Wih, wih, D3D);
    to_half_kernel<<<(D3D + 255) / 256, 256, 0, s2>>>(Whh, whh, D3D);
    cudaEventRecord(evJa[3], s2);

    // kproj -> e4m3, vproj -> fp16 -> transpose to e4m3
    launch_gemm4(pln_h, wk, 0, 0, pk8, N_IN, D_DIM, D_DIM, 1.0f, bk, 0, 0, 0);
    launch_gemm4(pln_h, wv, 0, pv_h, 0, N_IN, D_DIM, D_DIM, 1.0f, bv, 0, 0, 0);
    transpose_8<<<dim3(D_DIM / 32, N_IN / 32), dim3(32, 8)>>>(pv_h, pvT8);
    copy_both_kernel<<<(S_SLOTS * D_DIM) / 256, 256>>>(cand, pslots, pslots_h, S_SLOTS * D_DIM);
    cudaStreamWaitEvent(0, evJa[3], 0);

    for (int it = 0; it < 3; ++it) {
        // critical path: LN, qproj (-> e4m3), fp8 QK (+f16x2 exp -> e4m3 P)
        ln_h_kernel<<<S_SLOTS, 256>>>(pslots, gsl, besl, ptmp_h);
        launch_gemm2(ptmp_h, wq, 0, 0, pq8, S_SLOTS, D_DIM, D_DIM, 1.0f, bq, 0, 0, 0);
        {
            dim3 g(N_IN / BN, S_SLOTS / 128, 1);
            gemm_f8<4><<<g, 256, F8_SMEM_4>>>(pq8, pk8, 0, pp8, D_DIM, D_DIM, N_IN,
                                              scale, 1);
        }

        // fork after QK: rowsum then gh on s2
        cudaEventRecord(evF[it], 0);
        cudaStreamWaitEvent(s2, evF[it], 0);
        rowsum8_kernel<<<S_SLOTS, 256, 0, s2>>>(pp8, pl);
        cudaEventRecord(evJa[it], s2);
        launch_gemm4(pslots_h, whh, pgh, 0, 0, S_SLOTS, D3, D_DIM, 1.0f, bhh, 0, 0, 0, s2);
        cudaEventRecord(evJb[it], s2);

        // P@V split-K in fp8 (fp16 partials), reduce -> upd_h
        {
            dim3 g(D_DIM / BN, S_SLOTS / 64, PV_SPLIT);
            gemm_f8<2><<<g, 256, F8_SMEM_2>>>(pp8, pvT8, ppart, 0, PV_KSPLIT, N_IN,
                                              D_DIM, 1.0f, 0);
        }
        reduce_pv_kernel<<<(S_SLOTS * D_DIM / 2) / 256, 256>>>(ppart, pupd_h);

        // gx = (upd_raw @ Wih^T)/lsum + bih
        cudaStreamWaitEvent(0, evJa[it], 0);
        launch_gemm4(pupd_h, wih, pgx, 0, 0, S_SLOTS, D3, D_DIM, 1.0f, bih, pl, 0, 0);

        // fused GRU + ff-LN (needs gh)
        cudaStreamWaitEvent(0, evJb[it], 0);
        gru_ln_kernel<<<S_SLOTS, 256>>>(pgx, pgh, pslots, ph, gff, beff, ptmp_h);

        // slots = h + relu(LN(h) @ W1^T + b1) @ W2^T + b2
        launch_gemm2(ptmp_h, w1, 0, pt_h, 0, S_SLOTS, D_DIM, D_DIM, 1.0f, b1, 0, 0, 1);
        if (it == 2) {
            launch_gemm2(pt_h, w2, (float*)d_out, 0, 0, S_SLOTS, D_DIM, D_DIM, 1.0f, b2, 0, ph, 0);
        } else {
            launch_gemm2(pt_h, w2, pslots, pslots_h, 0, S_SLOTS, D_DIM, D_DIM, 1.0f, b2, 0, ph, 0);
        }
    }
}